// round 3
// baseline (speedup 1.0000x reference)
#include <cuda_runtime.h>
#include <math.h>

#define NN 50000
#define EE 400000

// ---------------- scratch (device globals) ----------------
// q|k|v|s slices, each NN*512 floats
__device__ float g_y[(size_t)NN * 2048];
__device__ float g_agg[(size_t)NN * 512];
__device__ float g_h[(size_t)NN * 512];
__device__ float g_alpha[(size_t)EE * 4];
__device__ float g_ex[(size_t)EE * 4];
__device__ float g_m[(size_t)NN * 4];
__device__ float g_den[(size_t)NN * 4];

__device__ __forceinline__ void atomicMaxF(float* addr, float val) {
    int* ia = (int*)addr;
    int old = *ia;
    while (__int_as_float(old) < val) {
        int assumed = old;
        old = atomicCAS(ia, assumed, __float_as_int(val));
        if (old == assumed) break;
    }
}

// ---------------- naive GEMM: out[M,F] = A[M,K] @ W[K,F] + b ----------------
__global__ void k_gemm_naive(const float* __restrict__ A, const float* __restrict__ W,
                             const float* __restrict__ b, float* __restrict__ out,
                             int M, int K, int F) {
    int idx = blockIdx.x * blockDim.x + threadIdx.x;
    if (idx >= M * F) return;
    int m = idx / F, f = idx % F;
    const float* a = A + (size_t)m * K;
    float s = b[f];
    for (int k = 0; k < K; k++) s = fmaf(a[k], W[(size_t)k * F + f], s);
    out[(size_t)m * F + f] = s;
}

// ---------------- per-(edge,head) attention score ----------------
__global__ void k_alpha(const int* __restrict__ src, const int* __restrict__ dst,
                        const float* __restrict__ q, const float* __restrict__ k,
                        int E, int H, int C, float scale) {
    int idx = blockIdx.x * blockDim.x + threadIdx.x;
    if (idx >= E * H) return;
    int e = idx / H, h = idx % H;
    int F = H * C;
    const float* qp = q + (size_t)dst[e] * F + h * C;
    const float* kp = k + (size_t)src[e] * F + h * C;
    float s = 0.f;
    for (int c = 0; c < C; c++) s = fmaf(qp[c], kp[c], s);
    g_alpha[idx] = s * scale;  // layout [e*H + h]
}

// ---------------- segment max / exp / segment sum (atomics) ----------------
__global__ void k_init_md(int n) {
    int i = blockIdx.x * blockDim.x + threadIdx.x;
    if (i < n) { g_m[i] = -INFINITY; g_den[i] = 0.f; }
}
__global__ void k_max(const int* __restrict__ dst, int E, int H) {
    int idx = blockIdx.x * blockDim.x + threadIdx.x;
    if (idx >= E * H) return;
    int e = idx / H, h = idx % H;
    atomicMaxF(&g_m[(size_t)dst[e] * H + h], g_alpha[idx]);
}
__global__ void k_ex(const int* __restrict__ dst, int E, int H) {
    int idx = blockIdx.x * blockDim.x + threadIdx.x;
    if (idx >= E * H) return;
    int e = idx / H, h = idx % H;
    float m = g_m[(size_t)dst[e] * H + h];
    float ex = expf(g_alpha[idx] - m);
    g_ex[idx] = ex;
    atomicAdd(&g_den[(size_t)dst[e] * H + h], ex);
}

__global__ void k_zero(float* p, int n) {
    int i = blockIdx.x * blockDim.x + threadIdx.x;
    if (i < n) p[i] = 0.f;
}

// ---------------- weighted aggregation: one thread per (e,h,c) ----------------
__global__ void k_aggregate(const int* __restrict__ src, const int* __restrict__ dst,
                            const float* __restrict__ v, int E, int H, int C) {
    int idx = blockIdx.x * blockDim.x + threadIdx.x;
    if (idx >= E * H * C) return;
    int c = idx % C;
    int eh = idx / C;
    int h = eh % H;
    int e = eh / H;
    int F = H * C;
    float den = g_den[(size_t)dst[e] * H + h];
    float w = g_ex[(size_t)e * H + h] / (den + 1e-16f);
    atomicAdd(&g_agg[(size_t)dst[e] * F + h * C + c],
              w * v[(size_t)src[e] * F + h * C + c]);
}

// ---------------- skip + LayerNorm + ELU (warp per node) ----------------
template <int F>
__global__ void k_post(const float* __restrict__ sskip,
                       const float* __restrict__ lng, const float* __restrict__ lnb, int n) {
    constexpr int CC = F / 32;
    int node = (blockIdx.x * blockDim.x + threadIdx.x) >> 5;
    int lane = threadIdx.x & 31;
    if (node >= n) return;
    float acc[CC];
#pragma unroll
    for (int cc = 0; cc < CC; cc++) {
        int ch = lane + 32 * cc;
        acc[cc] = g_agg[(size_t)node * F + ch] + sskip[(size_t)node * F + ch];
    }
    float s = 0.f;
#pragma unroll
    for (int cc = 0; cc < CC; cc++) s += acc[cc];
#pragma unroll
    for (int o = 16; o; o >>= 1) s += __shfl_xor_sync(0xffffffffu, s, o);
    float mean = s / (float)F;
    float vs = 0.f;
#pragma unroll
    for (int cc = 0; cc < CC; cc++) {
        float d = acc[cc] - mean;
        vs = fmaf(d, d, vs);
    }
#pragma unroll
    for (int o = 16; o; o >>= 1) vs += __shfl_xor_sync(0xffffffffu, vs, o);
    float r = rsqrtf(vs / (float)F + 1e-5f);
#pragma unroll
    for (int cc = 0; cc < CC; cc++) {
        int ch = lane + 32 * cc;
        float t = (acc[cc] - mean) * r * lng[ch] + lnb[ch];
        g_h[(size_t)node * F + ch] = t > 0.f ? t : expm1f(t);
    }
}

// ---------------- layer-3 finalize: skip + log_softmax ----------------
__global__ void k_final(const float* __restrict__ s3, float* __restrict__ out, int n) {
    int i = blockIdx.x * blockDim.x + threadIdx.x;
    if (i >= n) return;
    float h0 = g_agg[(size_t)i * 2 + 0] + s3[(size_t)i * 2 + 0];
    float h1 = g_agg[(size_t)i * 2 + 1] + s3[(size_t)i * 2 + 1];
    float mx = fmaxf(h0, h1);
    float lse = mx + logf(expf(h0 - mx) + expf(h1 - mx));
    out[2 * i + 0] = h0 - lse;
    out[2 * i + 1] = h1 - lse;
}

// ---------------- launch ----------------
static inline int cdiv(int a, int b) { return (a + b - 1) / b; }

extern "C" void kernel_launch(void* const* d_in, const int* in_sizes, int n_in,
                              void* d_out, int out_size) {
    const float* x = (const float*)d_in[0];
    const int* ei = (const int*)d_in[1];
    const int N = in_sizes[0] / 128;
    const int E = in_sizes[1] / 2;
    const int* src = ei;        // edge_index[0]
    const int* dst = ei + E;    // edge_index[1]

    const float *Wq1 = (const float*)d_in[2],  *bq1 = (const float*)d_in[3];
    const float *Wk1 = (const float*)d_in[4],  *bk1 = (const float*)d_in[5];
    const float *Wv1 = (const float*)d_in[6],  *bv1 = (const float*)d_in[7];
    const float *Ws1 = (const float*)d_in[8],  *bs1 = (const float*)d_in[9];
    const float *Wq2 = (const float*)d_in[10], *bq2 = (const float*)d_in[11];
    const float *Wk2 = (const float*)d_in[12], *bk2 = (const float*)d_in[13];
    const float *Wv2 = (const float*)d_in[14], *bv2 = (const float*)d_in[15];
    const float *Ws2 = (const float*)d_in[16], *bs2 = (const float*)d_in[17];
    const float *Wq3 = (const float*)d_in[18], *bq3 = (const float*)d_in[19];
    const float *Wk3 = (const float*)d_in[20], *bk3 = (const float*)d_in[21];
    const float *Wv3 = (const float*)d_in[22], *bv3 = (const float*)d_in[23];
    const float *Ws3 = (const float*)d_in[24], *bs3 = (const float*)d_in[25];
    const float *ln1g = (const float*)d_in[26], *ln1b = (const float*)d_in[27];
    const float *ln2g = (const float*)d_in[28], *ln2b = (const float*)d_in[29];
    float* out = (float*)d_out;

    // device-global slice pointers (resolved via symbol address arithmetic on device side
    // is not possible from host; instead use cudaGetSymbolAddress-free trick: pass offsets
    // through kernels that take float* — we obtain the base address with a tiny helper)
    // Simplest portable approach: use cudaGetSymbolAddress (allowed: no allocation).
    static float* yb = nullptr;
    if (!yb) { void* p; cudaGetSymbolAddress(&p, g_y); yb = (float*)p; }
    float* q = yb;
    float* k = yb + (size_t)NN * 512;
    float* v = yb + (size_t)NN * 1024;
    float* sOut = yb + (size_t)NN * 1536;
    static float* aggb = nullptr;
    if (!aggb) { void* p; cudaGetSymbolAddress(&p, g_agg); aggb = (float*)p; }
    static float* hb = nullptr;
    if (!hb) { void* p; cudaGetSymbolAddress(&p, g_h); hb = (float*)p; }

    const int TB = 256;

    // ================= layer 1: K=128, F=512, H=4, C=128 =================
    {
        int K = 128, F = 512, H = 4, C = 128;
        k_gemm_naive<<<cdiv(N * F, TB), TB>>>(x, Wq1, bq1, q, N, K, F);
        k_gemm_naive<<<cdiv(N * F, TB), TB>>>(x, Wk1, bk1, k, N, K, F);
        k_gemm_naive<<<cdiv(N * F, TB), TB>>>(x, Wv1, bv1, v, N, K, F);
        k_gemm_naive<<<cdiv(N * F, TB), TB>>>(x, Ws1, bs1, sOut, N, K, F);
        k_alpha<<<cdiv(E * H, TB), TB>>>(src, dst, q, k, E, H, C, (float)(1.0 / sqrt((double)C)));
        k_init_md<<<cdiv(N * H, TB), TB>>>(N * H);
        k_max<<<cdiv(E * H, TB), TB>>>(dst, E, H);
        k_ex<<<cdiv(E * H, TB), TB>>>(dst, E, H);
        k_zero<<<cdiv(N * F, TB), TB>>>(aggb, N * F);
        k_aggregate<<<cdiv(E * H * C, TB), TB>>>(src, dst, v, E, H, C);
        k_post<512><<<cdiv(N * 32, TB), TB>>>(sOut, ln1g, ln1b, N);
    }
    // ================= layer 2: K=512, F=256, H=4, C=64 =================
    {
        int K = 512, F = 256, H = 4, C = 64;
        k_gemm_naive<<<cdiv(N * F, TB), TB>>>(hb, Wq2, bq2, q, N, K, F);
        k_gemm_naive<<<cdiv(N * F, TB), TB>>>(hb, Wk2, bk2, k, N, K, F);
        k_gemm_naive<<<cdiv(N * F, TB), TB>>>(hb, Wv2, bv2, v, N, K, F);
        k_gemm_naive<<<cdiv(N * F, TB), TB>>>(hb, Ws2, bs2, sOut, N, K, F);
        k_alpha<<<cdiv(E * H, TB), TB>>>(src, dst, q, k, E, H, C, (float)(1.0 / sqrt((double)C)));
        k_init_md<<<cdiv(N * H, TB), TB>>>(N * H);
        k_max<<<cdiv(E * H, TB), TB>>>(dst, E, H);
        k_ex<<<cdiv(E * H, TB), TB>>>(dst, E, H);
        k_zero<<<cdiv(N * F, TB), TB>>>(aggb, N * F);
        k_aggregate<<<cdiv(E * H * C, TB), TB>>>(src, dst, v, E, H, C);
        k_post<256><<<cdiv(N * 32, TB), TB>>>(sOut, ln2g, ln2b, N);
    }
    // ================= layer 3: K=256, F=2, H=1, C=2 =================
    {
        int K = 256, F = 2, H = 1, C = 2;
        k_gemm_naive<<<cdiv(N * F, TB), TB>>>(hb, Wq3, bq3, q, N, K, F);
        k_gemm_naive<<<cdiv(N * F, TB), TB>>>(hb, Wk3, bk3, k, N, K, F);
        k_gemm_naive<<<cdiv(N * F, TB), TB>>>(hb, Wv3, bv3, v, N, K, F);
        k_gemm_naive<<<cdiv(N * F, TB), TB>>>(hb, Ws3, bs3, sOut, N, K, F);
        k_alpha<<<cdiv(E * H, TB), TB>>>(src, dst, q, k, E, H, C, (float)(1.0 / sqrt((double)C)));
        k_init_md<<<cdiv(N * H, TB), TB>>>(N * H);
        k_max<<<cdiv(E * H, TB), TB>>>(dst, E, H);
        k_ex<<<cdiv(E * H, TB), TB>>>(dst, E, H);
        k_zero<<<cdiv(N * F, TB), TB>>>(aggb, N * F);
        k_aggregate<<<cdiv(E * H * C, TB), TB>>>(src, dst, v, E, H, C);
        k_final<<<cdiv(N, TB), TB>>>(sOut, out, N);
    }
}

// round 4
// speedup vs baseline: 2.1966x; 2.1966x over previous
#include <cuda_runtime.h>
#include <math.h>

#define NN 50000
#define EE 400000

// ---------------- scratch (device globals) ----------------
__device__ float g_y[(size_t)NN * 2048];     // q|k|v|s slices, each NN*512
__device__ float g_agg[(size_t)NN * 512];
__device__ float g_h[(size_t)NN * 512];
__device__ float g_alpha[(size_t)EE * 4];
__device__ float g_ex[(size_t)EE * 4];
__device__ float g_m[(size_t)NN * 4];
__device__ float g_den[(size_t)NN * 4];

__device__ __forceinline__ void atomicMaxF(float* addr, float val) {
    int* ia = (int*)addr;
    int old = *ia;
    while (__int_as_float(old) < val) {
        int assumed = old;
        old = atomicCAS(ia, assumed, __float_as_int(val));
        if (old == assumed) break;
    }
}

// ---------------- tiled SGEMM: out[M,F] = A[M,K] @ W[K,F] + b ----------------
// 128x128 block tile, 8x8 per thread, BK=8, 256 threads. F must be multiple of 128,
// K multiple of 8. Guarded on M.
__global__ void __launch_bounds__(256) k_sgemm_t(const float* __restrict__ A,
                                                 const float* __restrict__ W,
                                                 const float* __restrict__ b,
                                                 float* __restrict__ out,
                                                 int M, int K, int F) {
    __shared__ __align__(16) float As[8][128];
    __shared__ __align__(16) float Bs[8][128];
    int tid = threadIdx.x;
    int bn = blockIdx.x, bm = blockIdx.y;
    int arow = tid >> 1;            // [0,128)
    int acol = (tid & 1) * 4;       // {0,4}
    int brow = tid >> 5;            // [0,8)
    int bcol = (tid & 31) * 4;      // [0,128)
    int gArow = bm * 128 + arow;
    int tx = tid & 15, ty = tid >> 4;

    float acc[8][8];
#pragma unroll
    for (int i = 0; i < 8; i++)
#pragma unroll
        for (int j = 0; j < 8; j++) acc[i][j] = 0.f;

    const float* Aptr = A + (size_t)gArow * K + acol;
    const float* Bptr = W + (size_t)brow * F + bn * 128 + bcol;

    for (int k0 = 0; k0 < K; k0 += 8) {
        float4 av = make_float4(0.f, 0.f, 0.f, 0.f);
        if (gArow < M) av = *(const float4*)(Aptr + k0);
        As[acol + 0][arow] = av.x;
        As[acol + 1][arow] = av.y;
        As[acol + 2][arow] = av.z;
        As[acol + 3][arow] = av.w;
        float4 bv = *(const float4*)(Bptr + (size_t)k0 * F);
        *(float4*)&Bs[brow][bcol] = bv;
        __syncthreads();
#pragma unroll
        for (int k = 0; k < 8; k++) {
            float4 a0 = *(const float4*)&As[k][ty * 4];
            float4 a1 = *(const float4*)&As[k][64 + ty * 4];
            float4 b0 = *(const float4*)&Bs[k][tx * 4];
            float4 b1 = *(const float4*)&Bs[k][64 + tx * 4];
            float ar[8] = {a0.x, a0.y, a0.z, a0.w, a1.x, a1.y, a1.z, a1.w};
            float br[8] = {b0.x, b0.y, b0.z, b0.w, b1.x, b1.y, b1.z, b1.w};
#pragma unroll
            for (int i = 0; i < 8; i++)
#pragma unroll
                for (int j = 0; j < 8; j++) acc[i][j] = fmaf(ar[i], br[j], acc[i][j]);
        }
        __syncthreads();
    }
#pragma unroll
    for (int iq = 0; iq < 2; iq++)
#pragma unroll
        for (int ii = 0; ii < 4; ii++) {
            int r = bm * 128 + iq * 64 + ty * 4 + ii;
            if (r >= M) continue;
#pragma unroll
            for (int jq = 0; jq < 2; jq++) {
                int c = bn * 128 + jq * 64 + tx * 4;
                float* op = out + (size_t)r * F + c;
                op[0] = acc[iq * 4 + ii][jq * 4 + 0] + b[c + 0];
                op[1] = acc[iq * 4 + ii][jq * 4 + 1] + b[c + 1];
                op[2] = acc[iq * 4 + ii][jq * 4 + 2] + b[c + 2];
                op[3] = acc[iq * 4 + ii][jq * 4 + 3] + b[c + 3];
            }
        }
}

// ---------------- naive GEMM (layer 3 only: F=2) ----------------
__global__ void k_gemm_naive(const float* __restrict__ A, const float* __restrict__ W,
                             const float* __restrict__ b, float* __restrict__ out,
                             int M, int K, int F) {
    int idx = blockIdx.x * blockDim.x + threadIdx.x;
    if (idx >= M * F) return;
    int m = idx / F, f = idx % F;
    const float* a = A + (size_t)m * K;
    float s = b[f];
    for (int k = 0; k < K; k++) s = fmaf(a[k], W[(size_t)k * F + f], s);
    out[(size_t)m * F + f] = s;
}

// ---------------- per-(edge,head) attention score ----------------
__global__ void k_alpha(const int* __restrict__ src, const int* __restrict__ dst,
                        const float* __restrict__ q, const float* __restrict__ k,
                        int E, int H, int C, float scale) {
    int idx = blockIdx.x * blockDim.x + threadIdx.x;
    if (idx >= E * H) return;
    int e = idx / H, h = idx % H;
    int F = H * C;
    const float* qp = q + (size_t)dst[e] * F + h * C;
    const float* kp = k + (size_t)src[e] * F + h * C;
    float s = 0.f;
    for (int c = 0; c < C; c++) s = fmaf(qp[c], kp[c], s);
    g_alpha[idx] = s * scale;  // layout [e*H + h]
}

// ---------------- segment max / exp / segment sum (atomics) ----------------
__global__ void k_init_md(int n) {
    int i = blockIdx.x * blockDim.x + threadIdx.x;
    if (i < n) { g_m[i] = -INFINITY; g_den[i] = 0.f; }
}
__global__ void k_max(const int* __restrict__ dst, int E, int H) {
    int idx = blockIdx.x * blockDim.x + threadIdx.x;
    if (idx >= E * H) return;
    int e = idx / H, h = idx % H;
    atomicMaxF(&g_m[(size_t)dst[e] * H + h], g_alpha[idx]);
}
__global__ void k_ex(const int* __restrict__ dst, int E, int H) {
    int idx = blockIdx.x * blockDim.x + threadIdx.x;
    if (idx >= E * H) return;
    int e = idx / H, h = idx % H;
    float m = g_m[(size_t)dst[e] * H + h];
    float ex = expf(g_alpha[idx] - m);
    g_ex[idx] = ex;
    atomicAdd(&g_den[(size_t)dst[e] * H + h], ex);
}

__global__ void k_zero(float* p, int n) {
    int i = blockIdx.x * blockDim.x + threadIdx.x;
    if (i < n) p[i] = 0.f;
}

// ---------------- weighted aggregation: one thread per (e,h,c) ----------------
__global__ void k_aggregate(const int* __restrict__ src, const int* __restrict__ dst,
                            const float* __restrict__ v, int E, int H, int C) {
    int idx = blockIdx.x * blockDim.x + threadIdx.x;
    if (idx >= E * H * C) return;
    int c = idx % C;
    int eh = idx / C;
    int h = eh % H;
    int e = eh / H;
    int F = H * C;
    float den = g_den[(size_t)dst[e] * H + h];
    float w = g_ex[(size_t)e * H + h] / (den + 1e-16f);
    atomicAdd(&g_agg[(size_t)dst[e] * F + h * C + c],
              w * v[(size_t)src[e] * F + h * C + c]);
}

// ---------------- skip + LayerNorm + ELU (warp per node) ----------------
template <int F>
__global__ void k_post(const float* __restrict__ sskip,
                       const float* __restrict__ lng, const float* __restrict__ lnb, int n) {
    constexpr int CC = F / 32;
    int node = (blockIdx.x * blockDim.x + threadIdx.x) >> 5;
    int lane = threadIdx.x & 31;
    if (node >= n) return;
    float acc[CC];
#pragma unroll
    for (int cc = 0; cc < CC; cc++) {
        int ch = lane + 32 * cc;
        acc[cc] = g_agg[(size_t)node * F + ch] + sskip[(size_t)node * F + ch];
    }
    float s = 0.f;
#pragma unroll
    for (int cc = 0; cc < CC; cc++) s += acc[cc];
#pragma unroll
    for (int o = 16; o; o >>= 1) s += __shfl_xor_sync(0xffffffffu, s, o);
    float mean = s / (float)F;
    float vs = 0.f;
#pragma unroll
    for (int cc = 0; cc < CC; cc++) {
        float d = acc[cc] - mean;
        vs = fmaf(d, d, vs);
    }
#pragma unroll
    for (int o = 16; o; o >>= 1) vs += __shfl_xor_sync(0xffffffffu, vs, o);
    float r = rsqrtf(vs / (float)F + 1e-5f);
#pragma unroll
    for (int cc = 0; cc < CC; cc++) {
        int ch = lane + 32 * cc;
        float t = (acc[cc] - mean) * r * lng[ch] + lnb[ch];
        g_h[(size_t)node * F + ch] = t > 0.f ? t : expm1f(t);
    }
}

// ---------------- layer-3 finalize: skip + log_softmax ----------------
__global__ void k_final(const float* __restrict__ s3, float* __restrict__ out, int n) {
    int i = blockIdx.x * blockDim.x + threadIdx.x;
    if (i >= n) return;
    float h0 = g_agg[(size_t)i * 2 + 0] + s3[(size_t)i * 2 + 0];
    float h1 = g_agg[(size_t)i * 2 + 1] + s3[(size_t)i * 2 + 1];
    float mx = fmaxf(h0, h1);
    float lse = mx + logf(expf(h0 - mx) + expf(h1 - mx));
    out[2 * i + 0] = h0 - lse;
    out[2 * i + 1] = h1 - lse;
}

// ---------------- launch ----------------
static inline int cdiv(int a, int b) { return (a + b - 1) / b; }

extern "C" void kernel_launch(void* const* d_in, const int* in_sizes, int n_in,
                              void* d_out, int out_size) {
    const float* x = (const float*)d_in[0];
    const int* ei = (const int*)d_in[1];
    const int N = in_sizes[0] / 128;
    const int E = in_sizes[1] / 2;
    const int* src = ei;        // edge_index[0]
    const int* dst = ei + E;    // edge_index[1]

    const float *Wq1 = (const float*)d_in[2],  *bq1 = (const float*)d_in[3];
    const float *Wk1 = (const float*)d_in[4],  *bk1 = (const float*)d_in[5];
    const float *Wv1 = (const float*)d_in[6],  *bv1 = (const float*)d_in[7];
    const float *Ws1 = (const float*)d_in[8],  *bs1 = (const float*)d_in[9];
    const float *Wq2 = (const float*)d_in[10], *bq2 = (const float*)d_in[11];
    const float *Wk2 = (const float*)d_in[12], *bk2 = (const float*)d_in[13];
    const float *Wv2 = (const float*)d_in[14], *bv2 = (const float*)d_in[15];
    const float *Ws2 = (const float*)d_in[16], *bs2 = (const float*)d_in[17];
    const float *Wq3 = (const float*)d_in[18], *bq3 = (const float*)d_in[19];
    const float *Wk3 = (const float*)d_in[20], *bk3 = (const float*)d_in[21];
    const float *Wv3 = (const float*)d_in[22], *bv3 = (const float*)d_in[23];
    const float *Ws3 = (const float*)d_in[24], *bs3 = (const float*)d_in[25];
    const float *ln1g = (const float*)d_in[26], *ln1b = (const float*)d_in[27];
    const float *ln2g = (const float*)d_in[28], *ln2b = (const float*)d_in[29];
    float* out = (float*)d_out;

    static float* yb = nullptr;
    if (!yb) { void* p; cudaGetSymbolAddress(&p, g_y); yb = (float*)p; }
    float* q = yb;
    float* k = yb + (size_t)NN * 512;
    float* v = yb + (size_t)NN * 1024;
    float* sOut = yb + (size_t)NN * 1536;
    static float* aggb = nullptr;
    if (!aggb) { void* p; cudaGetSymbolAddress(&p, g_agg); aggb = (float*)p; }
    static float* hb = nullptr;
    if (!hb) { void* p; cudaGetSymbolAddress(&p, g_h); hb = (float*)p; }

    const int TB = 256;

    // ================= layer 1: K=128, F=512, H=4, C=128 =================
    {
        int K = 128, F = 512, H = 4, C = 128;
        dim3 grid(F / 128, cdiv(N, 128));
        k_sgemm_t<<<grid, 256>>>(x, Wq1, bq1, q, N, K, F);
        k_sgemm_t<<<grid, 256>>>(x, Wk1, bk1, k, N, K, F);
        k_sgemm_t<<<grid, 256>>>(x, Wv1, bv1, v, N, K, F);
        k_sgemm_t<<<grid, 256>>>(x, Ws1, bs1, sOut, N, K, F);
        k_alpha<<<cdiv(E * H, TB), TB>>>(src, dst, q, k, E, H, C, (float)(1.0 / sqrt((double)C)));
        k_init_md<<<cdiv(N * H, TB), TB>>>(N * H);
        k_max<<<cdiv(E * H, TB), TB>>>(dst, E, H);
        k_ex<<<cdiv(E * H, TB), TB>>>(dst, E, H);
        k_zero<<<cdiv(N * F, TB), TB>>>(aggb, N * F);
        k_aggregate<<<cdiv(E * H * C, TB), TB>>>(src, dst, v, E, H, C);
        k_post<512><<<cdiv(N * 32, TB), TB>>>(sOut, ln1g, ln1b, N);
    }
    // ================= layer 2: K=512, F=256, H=4, C=64 =================
    {
        int K = 512, F = 256, H = 4, C = 64;
        dim3 grid(F / 128, cdiv(N, 128));
        k_sgemm_t<<<grid, 256>>>(hb, Wq2, bq2, q, N, K, F);
        k_sgemm_t<<<grid, 256>>>(hb, Wk2, bk2, k, N, K, F);
        k_sgemm_t<<<grid, 256>>>(hb, Wv2, bv2, v, N, K, F);
        k_sgemm_t<<<grid, 256>>>(hb, Ws2, bs2, sOut, N, K, F);
        k_alpha<<<cdiv(E * H, TB), TB>>>(src, dst, q, k, E, H, C, (float)(1.0 / sqrt((double)C)));
        k_init_md<<<cdiv(N * H, TB), TB>>>(N * H);
        k_max<<<cdiv(E * H, TB), TB>>>(dst, E, H);
        k_ex<<<cdiv(E * H, TB), TB>>>(dst, E, H);
        k_zero<<<cdiv(N * F, TB), TB>>>(aggb, N * F);
        k_aggregate<<<cdiv(E * H * C, TB), TB>>>(src, dst, v, E, H, C);
        k_post<256><<<cdiv(N * 32, TB), TB>>>(sOut, ln2g, ln2b, N);
    }
    // ================= layer 3: K=256, F=2, H=1, C=2 =================
    {
        int K = 256, F = 2, H = 1, C = 2;
        k_gemm_naive<<<cdiv(N * F, TB), TB>>>(hb, Wq3, bq3, q, N, K, F);
        k_gemm_naive<<<cdiv(N * F, TB), TB>>>(hb, Wk3, bk3, k, N, K, F);
        k_gemm_naive<<<cdiv(N * F, TB), TB>>>(hb, Wv3, bv3, v, N, K, F);
        k_gemm_naive<<<cdiv(N * F, TB), TB>>>(hb, Ws3, bs3, sOut, N, K, F);
        k_alpha<<<cdiv(E * H, TB), TB>>>(src, dst, q, k, E, H, C, (float)(1.0 / sqrt((double)C)));
        k_init_md<<<cdiv(N * H, TB), TB>>>(N * H);
        k_max<<<cdiv(E * H, TB), TB>>>(dst, E, H);
        k_ex<<<cdiv(E * H, TB), TB>>>(dst, E, H);
        k_zero<<<cdiv(N * F, TB), TB>>>(aggb, N * F);
        k_aggregate<<<cdiv(E * H * C, TB), TB>>>(src, dst, v, E, H, C);
        k_final<<<cdiv(N, TB), TB>>>(sOut, out, N);
    }
}

// round 5
// speedup vs baseline: 2.9680x; 1.3512x over previous
#include <cuda_runtime.h>
#include <math.h>

#define NN 50000
#define EE 400000

// ---------------- scratch (device globals) ----------------
__device__ float g_y[(size_t)NN * 2048];     // q|k|v|s slices, each NN*512
__device__ float g_h[(size_t)NN * 512];
__device__ float g_alpha[(size_t)EE * 4];
__device__ int   g_rowptr[NN + 1];
__device__ int   g_cursor[NN];
__device__ int   g_perm[EE];
__device__ int   g_chunksum[256];

// ---------------- CSR build (by dst) ----------------
__global__ void k_zero_rowptr(int n) {
    int i = blockIdx.x * blockDim.x + threadIdx.x;
    if (i < n) g_rowptr[i] = 0;
}
__global__ void k_count(const int* __restrict__ dst, int E) {
    int e = blockIdx.x * blockDim.x + threadIdx.x;
    if (e < E) atomicAdd(&g_rowptr[dst[e] + 1], 1);
}
__global__ void k_block_sums(int n) {
    __shared__ int sh[256];
    int i = blockIdx.x * 256 + threadIdx.x;
    sh[threadIdx.x] = (i < n) ? g_rowptr[i] : 0;
    __syncthreads();
    for (int o = 128; o > 0; o >>= 1) {
        if (threadIdx.x < o) sh[threadIdx.x] += sh[threadIdx.x + o];
        __syncthreads();
    }
    if (threadIdx.x == 0) g_chunksum[blockIdx.x] = sh[0];
}
__global__ void k_scan_chunks(int nch) {
    if (threadIdx.x == 0 && blockIdx.x == 0) {
        int running = 0;
        for (int i = 0; i < nch; i++) {
            int t = g_chunksum[i];
            g_chunksum[i] = running;
            running += t;
        }
    }
}
__global__ void k_block_scan(int n) {
    __shared__ int sh[256];
    int i = blockIdx.x * 256 + threadIdx.x;
    int t = threadIdx.x;
    sh[t] = (i < n) ? g_rowptr[i] : 0;
    __syncthreads();
    for (int o = 1; o < 256; o <<= 1) {
        int v = sh[t];
        int u = (t >= o) ? sh[t - o] : 0;
        __syncthreads();
        sh[t] = v + u;
        __syncthreads();
    }
    if (i < n) g_rowptr[i] = sh[t] + g_chunksum[blockIdx.x];
}
__global__ void k_cursor(int n) {
    int i = blockIdx.x * blockDim.x + threadIdx.x;
    if (i < n) g_cursor[i] = g_rowptr[i];
}
__global__ void k_scatter(const int* __restrict__ dst, int E) {
    int e = blockIdx.x * blockDim.x + threadIdx.x;
    if (e < E) {
        int p = atomicAdd(&g_cursor[dst[e]], 1);
        g_perm[p] = e;
    }
}

// ---------------- tiled SGEMM (unchanged from passing round 4) ----------------
__global__ void __launch_bounds__(256) k_sgemm_t(const float* __restrict__ A,
                                                 const float* __restrict__ W,
                                                 const float* __restrict__ b,
                                                 float* __restrict__ out,
                                                 int M, int K, int F) {
    __shared__ __align__(16) float As[8][128];
    __shared__ __align__(16) float Bs[8][128];
    int tid = threadIdx.x;
    int bn = blockIdx.x, bm = blockIdx.y;
    int arow = tid >> 1;
    int acol = (tid & 1) * 4;
    int brow = tid >> 5;
    int bcol = (tid & 31) * 4;
    int gArow = bm * 128 + arow;
    int tx = tid & 15, ty = tid >> 4;

    float acc[8][8];
#pragma unroll
    for (int i = 0; i < 8; i++)
#pragma unroll
        for (int j = 0; j < 8; j++) acc[i][j] = 0.f;

    const float* Aptr = A + (size_t)gArow * K + acol;
    const float* Bptr = W + (size_t)brow * F + bn * 128 + bcol;

    for (int k0 = 0; k0 < K; k0 += 8) {
        float4 av = make_float4(0.f, 0.f, 0.f, 0.f);
        if (gArow < M) av = *(const float4*)(Aptr + k0);
        As[acol + 0][arow] = av.x;
        As[acol + 1][arow] = av.y;
        As[acol + 2][arow] = av.z;
        As[acol + 3][arow] = av.w;
        float4 bv = *(const float4*)(Bptr + (size_t)k0 * F);
        *(float4*)&Bs[brow][bcol] = bv;
        __syncthreads();
#pragma unroll
        for (int k = 0; k < 8; k++) {
            float4 a0 = *(const float4*)&As[k][ty * 4];
            float4 a1 = *(const float4*)&As[k][64 + ty * 4];
            float4 b0 = *(const float4*)&Bs[k][tx * 4];
            float4 b1 = *(const float4*)&Bs[k][64 + tx * 4];
            float ar[8] = {a0.x, a0.y, a0.z, a0.w, a1.x, a1.y, a1.z, a1.w};
            float br[8] = {b0.x, b0.y, b0.z, b0.w, b1.x, b1.y, b1.z, b1.w};
#pragma unroll
            for (int i = 0; i < 8; i++)
#pragma unroll
                for (int j = 0; j < 8; j++) acc[i][j] = fmaf(ar[i], br[j], acc[i][j]);
        }
        __syncthreads();
    }
#pragma unroll
    for (int iq = 0; iq < 2; iq++)
#pragma unroll
        for (int ii = 0; ii < 4; ii++) {
            int r = bm * 128 + iq * 64 + ty * 4 + ii;
            if (r >= M) continue;
#pragma unroll
            for (int jq = 0; jq < 2; jq++) {
                int c = bn * 128 + jq * 64 + tx * 4;
                float* op = out + (size_t)r * F + c;
                op[0] = acc[iq * 4 + ii][jq * 4 + 0] + b[c + 0];
                op[1] = acc[iq * 4 + ii][jq * 4 + 1] + b[c + 1];
                op[2] = acc[iq * 4 + ii][jq * 4 + 2] + b[c + 2];
                op[3] = acc[iq * 4 + ii][jq * 4 + 3] + b[c + 3];
            }
        }
}

// ---------------- naive GEMM (layer 3 only: F=2) ----------------
__global__ void k_gemm_naive(const float* __restrict__ A, const float* __restrict__ W,
                             const float* __restrict__ b, float* __restrict__ out,
                             int M, int K, int F) {
    int idx = blockIdx.x * blockDim.x + threadIdx.x;
    if (idx >= M * F) return;
    int m = idx / F, f = idx % F;
    const float* a = A + (size_t)m * K;
    float s = b[f];
    for (int k = 0; k < K; k++) s = fmaf(a[k], W[(size_t)k * F + f], s);
    out[(size_t)m * F + f] = s;
}

// ---------------- per-(edge,head) attention score (unchanged, passing) ----------------
__global__ void k_alpha(const int* __restrict__ src, const int* __restrict__ dst,
                        const float* __restrict__ q, const float* __restrict__ k,
                        int E, int H, int C, float scale) {
    int idx = blockIdx.x * blockDim.x + threadIdx.x;
    if (idx >= E * H) return;
    int e = idx / H, h = idx % H;
    int F = H * C;
    const float* qp = q + (size_t)dst[e] * F + h * C;
    const float* kp = k + (size_t)src[e] * F + h * C;
    float s = 0.f;
    for (int c = 0; c < C; c++) s = fmaf(qp[c], kp[c], s);
    g_alpha[idx] = s * scale;
}

// ---------------- CSR warp-per-node: softmax + aggregate + skip + LN + ELU ----------------
template <int H, int C>
__global__ void k_aggC(const int* __restrict__ src,
                       const float* __restrict__ v, const float* __restrict__ sskip,
                       const float* __restrict__ lng, const float* __restrict__ lnb,
                       float* __restrict__ outp, int n) {
    constexpr int F = H * C, CC = F / 32;
    int node = (blockIdx.x * blockDim.x + threadIdx.x) >> 5;
    int lane = threadIdx.x & 31;
    if (node >= n) return;
    int s0 = g_rowptr[node], s1 = g_rowptr[node + 1], deg = s1 - s0;

    float m[H], dn[H];
#pragma unroll
    for (int h = 0; h < H; h++) {
        float mv = -INFINITY;
        for (int j = lane; j < deg; j += 32)
            mv = fmaxf(mv, g_alpha[(size_t)g_perm[s0 + j] * H + h]);
#pragma unroll
        for (int o = 16; o; o >>= 1) mv = fmaxf(mv, __shfl_xor_sync(0xffffffffu, mv, o));
        m[h] = mv;
        float sv = 0.f;
        for (int j = lane; j < deg; j += 32)
            sv += expf(g_alpha[(size_t)g_perm[s0 + j] * H + h] - mv);
#pragma unroll
        for (int o = 16; o; o >>= 1) sv += __shfl_xor_sync(0xffffffffu, sv, o);
        dn[h] = 1.f / (sv + 1e-16f);
    }

    float acc[CC];
#pragma unroll
    for (int cc = 0; cc < CC; cc++) acc[cc] = 0.f;

    for (int j = 0; j < deg; j++) {
        int e = g_perm[s0 + j];
        int sv = src[e];
        float w[H];
#pragma unroll
        for (int h = 0; h < H; h++)
            w[h] = expf(g_alpha[(size_t)e * H + h] - m[h]) * dn[h];
        const float* vr = v + (size_t)sv * F;
#pragma unroll
        for (int cc = 0; cc < CC; cc++)
            acc[cc] = fmaf(w[(32 * cc) / C], vr[lane + 32 * cc], acc[cc]);
    }
    // skip
    const float* sr = sskip + (size_t)node * F;
#pragma unroll
    for (int cc = 0; cc < CC; cc++) acc[cc] += sr[lane + 32 * cc];

    // LayerNorm + ELU
    float s = 0.f;
#pragma unroll
    for (int cc = 0; cc < CC; cc++) s += acc[cc];
#pragma unroll
    for (int o = 16; o; o >>= 1) s += __shfl_xor_sync(0xffffffffu, s, o);
    float mean = s / (float)F;
    float vs = 0.f;
#pragma unroll
    for (int cc = 0; cc < CC; cc++) {
        float d = acc[cc] - mean;
        vs = fmaf(d, d, vs);
    }
#pragma unroll
    for (int o = 16; o; o >>= 1) vs += __shfl_xor_sync(0xffffffffu, vs, o);
    float r = rsqrtf(vs / (float)F + 1e-5f);
#pragma unroll
    for (int cc = 0; cc < CC; cc++) {
        int ch = lane + 32 * cc;
        float t = (acc[cc] - mean) * r * lng[ch] + lnb[ch];
        outp[(size_t)node * F + ch] = t > 0.f ? t : expm1f(t);
    }
}

// ---------------- layer 3 CSR finalize: softmax+agg+skip+log_softmax ----------------
__global__ void k_final3(const int* __restrict__ src,
                         const float* __restrict__ v2, const float* __restrict__ s3,
                         float* __restrict__ out, int n) {
    int i = blockIdx.x * blockDim.x + threadIdx.x;
    if (i >= n) return;
    int s0 = g_rowptr[i], s1 = g_rowptr[i + 1];
    float m = -INFINITY;
    for (int j = s0; j < s1; j++) m = fmaxf(m, g_alpha[g_perm[j]]);
    float a0 = 0.f, a1 = 0.f;
    if (s1 > s0) {
        float dnm = 0.f;
        for (int j = s0; j < s1; j++) dnm += expf(g_alpha[g_perm[j]] - m);
        float inv = 1.f / (dnm + 1e-16f);
        for (int j = s0; j < s1; j++) {
            int e = g_perm[j];
            float w = expf(g_alpha[e] - m) * inv;
            const float* vr = v2 + (size_t)src[e] * 2;
            a0 = fmaf(w, vr[0], a0);
            a1 = fmaf(w, vr[1], a1);
        }
    }
    float h0 = a0 + s3[(size_t)i * 2 + 0];
    float h1 = a1 + s3[(size_t)i * 2 + 1];
    float mx = fmaxf(h0, h1);
    float lse = mx + logf(expf(h0 - mx) + expf(h1 - mx));
    out[2 * i + 0] = h0 - lse;
    out[2 * i + 1] = h1 - lse;
}

// ---------------- launch ----------------
static inline int cdiv(int a, int b) { return (a + b - 1) / b; }

extern "C" void kernel_launch(void* const* d_in, const int* in_sizes, int n_in,
                              void* d_out, int out_size) {
    const float* x = (const float*)d_in[0];
    const int* ei = (const int*)d_in[1];
    const int N = in_sizes[0] / 128;
    const int E = in_sizes[1] / 2;
    const int* src = ei;
    const int* dst = ei + E;

    const float *Wq1 = (const float*)d_in[2],  *bq1 = (const float*)d_in[3];
    const float *Wk1 = (const float*)d_in[4],  *bk1 = (const float*)d_in[5];
    const float *Wv1 = (const float*)d_in[6],  *bv1 = (const float*)d_in[7];
    const float *Ws1 = (const float*)d_in[8],  *bs1 = (const float*)d_in[9];
    const float *Wq2 = (const float*)d_in[10], *bq2 = (const float*)d_in[11];
    const float *Wk2 = (const float*)d_in[12], *bk2 = (const float*)d_in[13];
    const float *Wv2 = (const float*)d_in[14], *bv2 = (const float*)d_in[15];
    const float *Ws2 = (const float*)d_in[16], *bs2 = (const float*)d_in[17];
    const float *Wq3 = (const float*)d_in[18], *bq3 = (const float*)d_in[19];
    const float *Wk3 = (const float*)d_in[20], *bk3 = (const float*)d_in[21];
    const float *Wv3 = (const float*)d_in[22], *bv3 = (const float*)d_in[23];
    const float *Ws3 = (const float*)d_in[24], *bs3 = (const float*)d_in[25];
    const float *ln1g = (const float*)d_in[26], *ln1b = (const float*)d_in[27];
    const float *ln2g = (const float*)d_in[28], *ln2b = (const float*)d_in[29];
    float* out = (float*)d_out;

    static float* yb = nullptr;
    if (!yb) { void* p; cudaGetSymbolAddress(&p, g_y); yb = (float*)p; }
    float* q = yb;
    float* k = yb + (size_t)NN * 512;
    float* v = yb + (size_t)NN * 1024;
    float* sOut = yb + (size_t)NN * 1536;
    static float* hb = nullptr;
    if (!hb) { void* p; cudaGetSymbolAddress(&p, g_h); hb = (float*)p; }

    const int TB = 256;

    // CSR build by dst (used by all 3 layers)
    int n1 = N + 1;
    int nch = cdiv(n1, 256);
    k_zero_rowptr<<<cdiv(n1, TB), TB>>>(n1);
    k_count<<<cdiv(E, TB), TB>>>(dst, E);
    k_block_sums<<<nch, 256>>>(n1);
    k_scan_chunks<<<1, 32>>>(nch);
    k_block_scan<<<nch, 256>>>(n1);
    k_cursor<<<cdiv(N, TB), TB>>>(N);
    k_scatter<<<cdiv(E, TB), TB>>>(dst, E);

    // ================= layer 1: K=128, F=512, H=4, C=128 =================
    {
        int K = 128, F = 512, H = 4, C = 128;
        dim3 grid(F / 128, cdiv(N, 128));
        k_sgemm_t<<<grid, 256>>>(x, Wq1, bq1, q, N, K, F);
        k_sgemm_t<<<grid, 256>>>(x, Wk1, bk1, k, N, K, F);
        k_sgemm_t<<<grid, 256>>>(x, Wv1, bv1, v, N, K, F);
        k_sgemm_t<<<grid, 256>>>(x, Ws1, bs1, sOut, N, K, F);
        k_alpha<<<cdiv(E * H, TB), TB>>>(src, dst, q, k, E, H, C, (float)(1.0 / sqrt((double)C)));
        k_aggC<4, 128><<<cdiv(N * 32, TB), TB>>>(src, v, sOut, ln1g, ln1b, hb, N);
    }
    // ================= layer 2: K=512, F=256, H=4, C=64 =================
    {
        int K = 512, F = 256, H = 4, C = 64;
        dim3 grid(F / 128, cdiv(N, 128));
        k_sgemm_t<<<grid, 256>>>(hb, Wq2, bq2, q, N, K, F);
        k_sgemm_t<<<grid, 256>>>(hb, Wk2, bk2, k, N, K, F);
        k_sgemm_t<<<grid, 256>>>(hb, Wv2, bv2, v, N, K, F);
        k_sgemm_t<<<grid, 256>>>(hb, Ws2, bs2, sOut, N, K, F);
        k_alpha<<<cdiv(E * H, TB), TB>>>(src, dst, q, k, E, H, C, (float)(1.0 / sqrt((double)C)));
        k_aggC<4, 64><<<cdiv(N * 32, TB), TB>>>(src, v, sOut, ln2g, ln2b, hb, N);
    }
    // ================= layer 3: K=256, F=2, H=1, C=2 =================
    {
        int K = 256, F = 2, H = 1, C = 2;
        k_gemm_naive<<<cdiv(N * F, TB), TB>>>(hb, Wq3, bq3, q, N, K, F);
        k_gemm_naive<<<cdiv(N * F, TB), TB>>>(hb, Wk3, bk3, k, N, K, F);
        k_gemm_naive<<<cdiv(N * F, TB), TB>>>(hb, Wv3, bv3, v, N, K, F);
        k_gemm_naive<<<cdiv(N * F, TB), TB>>>(hb, Ws3, bs3, sOut, N, K, F);
        k_alpha<<<cdiv(E * H, TB), TB>>>(src, dst, q, k, E, H, C, (float)(1.0 / sqrt((double)C)));
        k_final3<<<cdiv(N, TB), TB>>>(src, v, sOut, out, N);
    }
}

// round 6
// speedup vs baseline: 4.6274x; 1.5591x over previous
#include <cuda_runtime.h>
#include <math.h>

#define NN 50000
#define EE 400000

// ---------------- scratch (device globals) ----------------
__device__ float g_y[(size_t)NN * 2048];     // q|k|v|s slices, each NN*512
__device__ float g_h[(size_t)NN * 512];
__device__ float g_alpha[(size_t)EE * 4];
__device__ int   g_rowptr[NN + 1];
__device__ int   g_cursor[NN];
__device__ int   g_perm[EE];
__device__ int   g_chunksum[256];

// ---------------- CSR build (by dst) ----------------
__global__ void k_zero_rowptr(int n) {
    int i = blockIdx.x * blockDim.x + threadIdx.x;
    if (i < n) g_rowptr[i] = 0;
}
__global__ void k_count(const int* __restrict__ dst, int E) {
    int e = blockIdx.x * blockDim.x + threadIdx.x;
    if (e < E) atomicAdd(&g_rowptr[dst[e] + 1], 1);
}
__global__ void k_block_sums(int n) {
    __shared__ int sh[256];
    int i = blockIdx.x * 256 + threadIdx.x;
    sh[threadIdx.x] = (i < n) ? g_rowptr[i] : 0;
    __syncthreads();
    for (int o = 128; o > 0; o >>= 1) {
        if (threadIdx.x < o) sh[threadIdx.x] += sh[threadIdx.x + o];
        __syncthreads();
    }
    if (threadIdx.x == 0) g_chunksum[blockIdx.x] = sh[0];
}
__global__ void k_scan_chunks(int nch) {
    if (threadIdx.x == 0 && blockIdx.x == 0) {
        int running = 0;
        for (int i = 0; i < nch; i++) {
            int t = g_chunksum[i];
            g_chunksum[i] = running;
            running += t;
        }
    }
}
__global__ void k_block_scan(int n) {
    __shared__ int sh[256];
    int i = blockIdx.x * 256 + threadIdx.x;
    int t = threadIdx.x;
    sh[t] = (i < n) ? g_rowptr[i] : 0;
    __syncthreads();
    for (int o = 1; o < 256; o <<= 1) {
        int v = sh[t];
        int u = (t >= o) ? sh[t - o] : 0;
        __syncthreads();
        sh[t] = v + u;
        __syncthreads();
    }
    if (i < n) g_rowptr[i] = sh[t] + g_chunksum[blockIdx.x];
}
__global__ void k_cursor(int n) {
    int i = blockIdx.x * blockDim.x + threadIdx.x;
    if (i < n) g_cursor[i] = g_rowptr[i];
}
__global__ void k_scatter(const int* __restrict__ dst, int E) {
    int e = blockIdx.x * blockDim.x + threadIdx.x;
    if (e < E) {
        int p = atomicAdd(&g_cursor[dst[e]], 1);
        g_perm[p] = e;
    }
}

// ---------------- tiled SGEMM (unchanged, passing) ----------------
__global__ void __launch_bounds__(256) k_sgemm_t(const float* __restrict__ A,
                                                 const float* __restrict__ W,
                                                 const float* __restrict__ b,
                                                 float* __restrict__ out,
                                                 int M, int K, int F) {
    __shared__ __align__(16) float As[8][128];
    __shared__ __align__(16) float Bs[8][128];
    int tid = threadIdx.x;
    int bn = blockIdx.x, bm = blockIdx.y;
    int arow = tid >> 1;
    int acol = (tid & 1) * 4;
    int brow = tid >> 5;
    int bcol = (tid & 31) * 4;
    int gArow = bm * 128 + arow;
    int tx = tid & 15, ty = tid >> 4;

    float acc[8][8];
#pragma unroll
    for (int i = 0; i < 8; i++)
#pragma unroll
        for (int j = 0; j < 8; j++) acc[i][j] = 0.f;

    const float* Aptr = A + (size_t)gArow * K + acol;
    const float* Bptr = W + (size_t)brow * F + bn * 128 + bcol;

    for (int k0 = 0; k0 < K; k0 += 8) {
        float4 av = make_float4(0.f, 0.f, 0.f, 0.f);
        if (gArow < M) av = *(const float4*)(Aptr + k0);
        As[acol + 0][arow] = av.x;
        As[acol + 1][arow] = av.y;
        As[acol + 2][arow] = av.z;
        As[acol + 3][arow] = av.w;
        float4 bv = *(const float4*)(Bptr + (size_t)k0 * F);
        *(float4*)&Bs[brow][bcol] = bv;
        __syncthreads();
#pragma unroll
        for (int k = 0; k < 8; k++) {
            float4 a0 = *(const float4*)&As[k][ty * 4];
            float4 a1 = *(const float4*)&As[k][64 + ty * 4];
            float4 b0 = *(const float4*)&Bs[k][tx * 4];
            float4 b1 = *(const float4*)&Bs[k][64 + tx * 4];
            float ar[8] = {a0.x, a0.y, a0.z, a0.w, a1.x, a1.y, a1.z, a1.w};
            float br[8] = {b0.x, b0.y, b0.z, b0.w, b1.x, b1.y, b1.z, b1.w};
#pragma unroll
            for (int i = 0; i < 8; i++)
#pragma unroll
                for (int j = 0; j < 8; j++) acc[i][j] = fmaf(ar[i], br[j], acc[i][j]);
        }
        __syncthreads();
    }
#pragma unroll
    for (int iq = 0; iq < 2; iq++)
#pragma unroll
        for (int ii = 0; ii < 4; ii++) {
            int r = bm * 128 + iq * 64 + ty * 4 + ii;
            if (r >= M) continue;
#pragma unroll
            for (int jq = 0; jq < 2; jq++) {
                int c = bn * 128 + jq * 64 + tx * 4;
                float* op = out + (size_t)r * F + c;
                op[0] = acc[iq * 4 + ii][jq * 4 + 0] + b[c + 0];
                op[1] = acc[iq * 4 + ii][jq * 4 + 1] + b[c + 1];
                op[2] = acc[iq * 4 + ii][jq * 4 + 2] + b[c + 2];
                op[3] = acc[iq * 4 + ii][jq * 4 + 3] + b[c + 3];
            }
        }
}

// ---------------- naive GEMM (layer 3 only: F=2) ----------------
__global__ void k_gemm_naive(const float* __restrict__ A, const float* __restrict__ W,
                             const float* __restrict__ b, float* __restrict__ out,
                             int M, int K, int F) {
    int idx = blockIdx.x * blockDim.x + threadIdx.x;
    if (idx >= M * F) return;
    int m = idx / F, f = idx % F;
    const float* a = A + (size_t)m * K;
    float s = b[f];
    for (int k = 0; k < K; k++) s = fmaf(a[k], W[(size_t)k * F + f], s);
    out[(size_t)m * F + f] = s;
}

// ---------------- warp-per-edge attention score (float4, coalesced) ----------------
template <int H, int C>
__global__ void k_alpha_w(const int* __restrict__ src, const int* __restrict__ dst,
                          const float* __restrict__ q, const float* __restrict__ k,
                          int E, float scale) {
    constexpr int F = H * C;
    constexpr int T = F / 128;   // float4 iterations per lane (layer1: 4, layer2: 2)
    int e = (blockIdx.x * blockDim.x + threadIdx.x) >> 5;
    int lane = threadIdx.x & 31;
    if (e >= E) return;
    const float4* qp = (const float4*)(q + (size_t)dst[e] * F);
    const float4* kp = (const float4*)(k + (size_t)src[e] * F);
    float acc[H];
#pragma unroll
    for (int h = 0; h < H; h++) acc[h] = 0.f;
#pragma unroll
    for (int t = 0; t < T; t++) {
        int i = lane + 32 * t;
        float4 a = qp[i], b = kp[i];
        float d = a.x * b.x + a.y * b.y + a.z * b.z + a.w * b.w;
        if constexpr (C == 128) {
            // i/(C/4) = (lane+32t)/32 = t  (lane < 32)
            acc[t] += d;
        } else {
            // C == 64: head = (lane+32t)/16 = 2t + (lane>=16)
            if (lane < 16) acc[2 * t] += d;
            else acc[2 * t + 1] += d;
        }
    }
#pragma unroll
    for (int h = 0; h < H; h++) {
        float v = acc[h];
#pragma unroll
        for (int o = 16; o; o >>= 1) v += __shfl_xor_sync(0xffffffffu, v, o);
        if (lane == 0) g_alpha[(size_t)e * H + h] = v * scale;
    }
}

// ---------------- layer-3 score: thread-per-edge (C=2, trivial) ----------------
__global__ void k_alpha3(const int* __restrict__ src, const int* __restrict__ dst,
                         const float* __restrict__ q, const float* __restrict__ k,
                         int E, float scale) {
    int e = blockIdx.x * blockDim.x + threadIdx.x;
    if (e >= E) return;
    const float* qp = q + (size_t)dst[e] * 2;
    const float* kp = k + (size_t)src[e] * 2;
    g_alpha[e] = (qp[0] * kp[0] + qp[1] * kp[1]) * scale;
}

// ---------------- CSR warp-per-node: softmax + aggregate + skip + LN + ELU ----------------
template <int H, int C>
__global__ void k_aggC(const int* __restrict__ src,
                       const float* __restrict__ v, const float* __restrict__ sskip,
                       const float* __restrict__ lng, const float* __restrict__ lnb,
                       float* __restrict__ outp, int n) {
    constexpr int F = H * C, CC = F / 32;
    int node = (blockIdx.x * blockDim.x + threadIdx.x) >> 5;
    int lane = threadIdx.x & 31;
    if (node >= n) return;
    int s0 = g_rowptr[node], s1 = g_rowptr[node + 1], deg = s1 - s0;

    float m[H], dn[H];
#pragma unroll
    for (int h = 0; h < H; h++) {
        float mv = -INFINITY;
        for (int j = lane; j < deg; j += 32)
            mv = fmaxf(mv, g_alpha[(size_t)g_perm[s0 + j] * H + h]);
#pragma unroll
        for (int o = 16; o; o >>= 1) mv = fmaxf(mv, __shfl_xor_sync(0xffffffffu, mv, o));
        m[h] = mv;
        float sv = 0.f;
        for (int j = lane; j < deg; j += 32)
            sv += expf(g_alpha[(size_t)g_perm[s0 + j] * H + h] - mv);
#pragma unroll
        for (int o = 16; o; o >>= 1) sv += __shfl_xor_sync(0xffffffffu, sv, o);
        dn[h] = 1.f / (sv + 1e-16f);
    }

    float acc[CC];
#pragma unroll
    for (int cc = 0; cc < CC; cc++) acc[cc] = 0.f;

    for (int j = 0; j < deg; j++) {
        int e = g_perm[s0 + j];
        int sv = src[e];
        float w[H];
#pragma unroll
        for (int h = 0; h < H; h++)
            w[h] = expf(g_alpha[(size_t)e * H + h] - m[h]) * dn[h];
        const float* vr = v + (size_t)sv * F;
#pragma unroll
        for (int cc = 0; cc < CC; cc++)
            acc[cc] = fmaf(w[(32 * cc) / C], vr[lane + 32 * cc], acc[cc]);
    }
    // skip
    const float* sr = sskip + (size_t)node * F;
#pragma unroll
    for (int cc = 0; cc < CC; cc++) acc[cc] += sr[lane + 32 * cc];

    // LayerNorm + ELU
    float s = 0.f;
#pragma unroll
    for (int cc = 0; cc < CC; cc++) s += acc[cc];
#pragma unroll
    for (int o = 16; o; o >>= 1) s += __shfl_xor_sync(0xffffffffu, s, o);
    float mean = s / (float)F;
    float vs = 0.f;
#pragma unroll
    for (int cc = 0; cc < CC; cc++) {
        float d = acc[cc] - mean;
        vs = fmaf(d, d, vs);
    }
#pragma unroll
    for (int o = 16; o; o >>= 1) vs += __shfl_xor_sync(0xffffffffu, vs, o);
    float r = rsqrtf(vs / (float)F + 1e-5f);
#pragma unroll
    for (int cc = 0; cc < CC; cc++) {
        int ch = lane + 32 * cc;
        float t = (acc[cc] - mean) * r * lng[ch] + lnb[ch];
        outp[(size_t)node * F + ch] = t > 0.f ? t : expm1f(t);
    }
}

// ---------------- layer 3 CSR finalize: softmax+agg+skip+log_softmax ----------------
__global__ void k_final3(const int* __restrict__ src,
                         const float* __restrict__ v2, const float* __restrict__ s3,
                         float* __restrict__ out, int n) {
    int i = blockIdx.x * blockDim.x + threadIdx.x;
    if (i >= n) return;
    int s0 = g_rowptr[i], s1 = g_rowptr[i + 1];
    float m = -INFINITY;
    for (int j = s0; j < s1; j++) m = fmaxf(m, g_alpha[g_perm[j]]);
    float a0 = 0.f, a1 = 0.f;
    if (s1 > s0) {
        float dnm = 0.f;
        for (int j = s0; j < s1; j++) dnm += expf(g_alpha[g_perm[j]] - m);
        float inv = 1.f / (dnm + 1e-16f);
        for (int j = s0; j < s1; j++) {
            int e = g_perm[j];
            float w = expf(g_alpha[e] - m) * inv;
            const float* vr = v2 + (size_t)src[e] * 2;
            a0 = fmaf(w, vr[0], a0);
            a1 = fmaf(w, vr[1], a1);
        }
    }
    float h0 = a0 + s3[(size_t)i * 2 + 0];
    float h1 = a1 + s3[(size_t)i * 2 + 1];
    float mx = fmaxf(h0, h1);
    float lse = mx + logf(expf(h0 - mx) + expf(h1 - mx));
    out[2 * i + 0] = h0 - lse;
    out[2 * i + 1] = h1 - lse;
}

// ---------------- launch ----------------
static inline int cdiv(int a, int b) { return (a + b - 1) / b; }

extern "C" void kernel_launch(void* const* d_in, const int* in_sizes, int n_in,
                              void* d_out, int out_size) {
    const float* x = (const float*)d_in[0];
    const int* ei = (const int*)d_in[1];
    const int N = in_sizes[0] / 128;
    const int E = in_sizes[1] / 2;
    const int* src = ei;
    const int* dst = ei + E;

    const float *Wq1 = (const float*)d_in[2],  *bq1 = (const float*)d_in[3];
    const float *Wk1 = (const float*)d_in[4],  *bk1 = (const float*)d_in[5];
    const float *Wv1 = (const float*)d_in[6],  *bv1 = (const float*)d_in[7];
    const float *Ws1 = (const float*)d_in[8],  *bs1 = (const float*)d_in[9];
    const float *Wq2 = (const float*)d_in[10], *bq2 = (const float*)d_in[11];
    const float *Wk2 = (const float*)d_in[12], *bk2 = (const float*)d_in[13];
    const float *Wv2 = (const float*)d_in[14], *bv2 = (const float*)d_in[15];
    const float *Ws2 = (const float*)d_in[16], *bs2 = (const float*)d_in[17];
    const float *Wq3 = (const float*)d_in[18], *bq3 = (const float*)d_in[19];
    const float *Wk3 = (const float*)d_in[20], *bk3 = (const float*)d_in[21];
    const float *Wv3 = (const float*)d_in[22], *bv3 = (const float*)d_in[23];
    const float *Ws3 = (const float*)d_in[24], *bs3 = (const float*)d_in[25];
    const float *ln1g = (const float*)d_in[26], *ln1b = (const float*)d_in[27];
    const float *ln2g = (const float*)d_in[28], *ln2b = (const float*)d_in[29];
    float* out = (float*)d_out;

    static float* yb = nullptr;
    if (!yb) { void* p; cudaGetSymbolAddress(&p, g_y); yb = (float*)p; }
    float* q = yb;
    float* k = yb + (size_t)NN * 512;
    float* v = yb + (size_t)NN * 1024;
    float* sOut = yb + (size_t)NN * 1536;
    static float* hb = nullptr;
    if (!hb) { void* p; cudaGetSymbolAddress(&p, g_h); hb = (float*)p; }

    const int TB = 256;

    // CSR build by dst (used by all 3 layers)
    int n1 = N + 1;
    int nch = cdiv(n1, 256);
    k_zero_rowptr<<<cdiv(n1, TB), TB>>>(n1);
    k_count<<<cdiv(E, TB), TB>>>(dst, E);
    k_block_sums<<<nch, 256>>>(n1);
    k_scan_chunks<<<1, 32>>>(nch);
    k_block_scan<<<nch, 256>>>(n1);
    k_cursor<<<cdiv(N, TB), TB>>>(N);
    k_scatter<<<cdiv(E, TB), TB>>>(dst, E);

    // ================= layer 1: K=128, F=512, H=4, C=128 =================
    {
        int K = 128, F = 512;
        dim3 grid(F / 128, cdiv(N, 128));
        k_sgemm_t<<<grid, 256>>>(x, Wq1, bq1, q, N, K, F);
        k_sgemm_t<<<grid, 256>>>(x, Wk1, bk1, k, N, K, F);
        k_sgemm_t<<<grid, 256>>>(x, Wv1, bv1, v, N, K, F);
        k_sgemm_t<<<grid, 256>>>(x, Ws1, bs1, sOut, N, K, F);
        k_alpha_w<4, 128><<<cdiv(E * 32, TB), TB>>>(src, dst, q, k, E, 0.08838834764831845f);  // 1/sqrt(128)
        k_aggC<4, 128><<<cdiv(N * 32, TB), TB>>>(src, v, sOut, ln1g, ln1b, hb, N);
    }
    // ================= layer 2: K=512, F=256, H=4, C=64 =================
    {
        int K = 512, F = 256;
        dim3 grid(F / 128, cdiv(N, 128));
        k_sgemm_t<<<grid, 256>>>(hb, Wq2, bq2, q, N, K, F);
        k_sgemm_t<<<grid, 256>>>(hb, Wk2, bk2, k, N, K, F);
        k_sgemm_t<<<grid, 256>>>(hb, Wv2, bv2, v, N, K, F);
        k_sgemm_t<<<grid, 256>>>(hb, Ws2, bs2, sOut, N, K, F);
        k_alpha_w<4, 64><<<cdiv(E * 32, TB), TB>>>(src, dst, q, k, E, 0.125f);  // 1/sqrt(64)
        k_aggC<4, 64><<<cdiv(N * 32, TB), TB>>>(src, v, sOut, ln2g, ln2b, hb, N);
    }
    // ================= layer 3: K=256, F=2, H=1, C=2 =================
    {
        int K = 256, F = 2;
        k_gemm_naive<<<cdiv(N * F, TB), TB>>>(hb, Wq3, bq3, q, N, K, F);
        k_gemm_naive<<<cdiv(N * F, TB), TB>>>(hb, Wk3, bk3, k, N, K, F);
        k_gemm_naive<<<cdiv(N * F, TB), TB>>>(hb, Wv3, bv3, v, N, K, F);
        k_gemm_naive<<<cdiv(N * F, TB), TB>>>(hb, Ws3, bs3, sOut, N, K, F);
        k_alpha3<<<cdiv(E, TB), TB>>>(src, dst, q, k, E, 0.7071067811865475f);  // 1/sqrt(2)
        k_final3<<<cdiv(N, TB), TB>>>(src, v, sOut, out, N);
    }
}

// round 7
// speedup vs baseline: 5.7847x; 1.2501x over previous
#include <cuda_runtime.h>
#include <math.h>

#define NN 50000
#define EE 400000

// ---------------- scratch (device globals) ----------------
__device__ float g_y[(size_t)NN * 2048];     // q|k|v|s slices, each NN*512
__device__ float g_h[(size_t)NN * 512];
__device__ float g_alpha[(size_t)EE * 4];
__device__ int   g_rowptr[NN + 1];
__device__ int   g_cursor[NN];
__device__ int   g_perm[EE];
__device__ int   g_chunksum[256];

// ---------------- CSR build (by dst) ----------------
__global__ void k_zero_rowptr(int n) {
    int i = blockIdx.x * blockDim.x + threadIdx.x;
    if (i < n) g_rowptr[i] = 0;
}
__global__ void k_count(const int* __restrict__ dst, int E) {
    int e = blockIdx.x * blockDim.x + threadIdx.x;
    if (e < E) atomicAdd(&g_rowptr[dst[e] + 1], 1);
}
__global__ void k_block_sums(int n) {
    __shared__ int sh[256];
    int i = blockIdx.x * 256 + threadIdx.x;
    sh[threadIdx.x] = (i < n) ? g_rowptr[i] : 0;
    __syncthreads();
    for (int o = 128; o > 0; o >>= 1) {
        if (threadIdx.x < o) sh[threadIdx.x] += sh[threadIdx.x + o];
        __syncthreads();
    }
    if (threadIdx.x == 0) g_chunksum[blockIdx.x] = sh[0];
}
__global__ void k_scan_chunks(int nch) {
    if (threadIdx.x == 0 && blockIdx.x == 0) {
        int running = 0;
        for (int i = 0; i < nch; i++) {
            int t = g_chunksum[i];
            g_chunksum[i] = running;
            running += t;
        }
    }
}
__global__ void k_block_scan(int n) {
    __shared__ int sh[256];
    int i = blockIdx.x * 256 + threadIdx.x;
    int t = threadIdx.x;
    sh[t] = (i < n) ? g_rowptr[i] : 0;
    __syncthreads();
    for (int o = 1; o < 256; o <<= 1) {
        int v = sh[t];
        int u = (t >= o) ? sh[t - o] : 0;
        __syncthreads();
        sh[t] = v + u;
        __syncthreads();
    }
    if (i < n) g_rowptr[i] = sh[t] + g_chunksum[blockIdx.x];
}
__global__ void k_cursor(int n) {
    int i = blockIdx.x * blockDim.x + threadIdx.x;
    if (i < n) g_cursor[i] = g_rowptr[i];
}
__global__ void k_scatter(const int* __restrict__ dst, int E) {
    int e = blockIdx.x * blockDim.x + threadIdx.x;
    if (e < E) {
        int p = atomicAdd(&g_cursor[dst[e]], 1);
        g_perm[p] = e;
    }
}

// ---------------- fused 4-way tiled SGEMM: {q,k,v,s}[M,F] = A[M,K] @ W{q,k,v,s}[K,F] + b ----
// grid.x = 4*(F/128); column-block bn selects which weight/output matrix.
__global__ void __launch_bounds__(256) k_sgemm4(const float* __restrict__ A,
                                                const float* __restrict__ W0, const float* __restrict__ b0, float* __restrict__ o0,
                                                const float* __restrict__ W1, const float* __restrict__ b1, float* __restrict__ o1,
                                                const float* __restrict__ W2, const float* __restrict__ b2, float* __restrict__ o2,
                                                const float* __restrict__ W3, const float* __restrict__ b3, float* __restrict__ o3,
                                                int M, int K, int F) {
    __shared__ __align__(16) float As[8][128];
    __shared__ __align__(16) float Bs[8][128];
    int tid = threadIdx.x;
    int nb = F / 128;                 // column blocks per matrix
    int bsel = blockIdx.x / nb;       // which of q/k/v/s
    int bn = blockIdx.x % nb;
    int bm = blockIdx.y;
    const float* W = bsel == 0 ? W0 : bsel == 1 ? W1 : bsel == 2 ? W2 : W3;
    const float* b = bsel == 0 ? b0 : bsel == 1 ? b1 : bsel == 2 ? b2 : b3;
    float* outp    = bsel == 0 ? o0 : bsel == 1 ? o1 : bsel == 2 ? o2 : o3;

    int arow = tid >> 1;
    int acol = (tid & 1) * 4;
    int brow = tid >> 5;
    int bcol = (tid & 31) * 4;
    int gArow = bm * 128 + arow;
    int tx = tid & 15, ty = tid >> 4;

    float acc[8][8];
#pragma unroll
    for (int i = 0; i < 8; i++)
#pragma unroll
        for (int j = 0; j < 8; j++) acc[i][j] = 0.f;

    const float* Aptr = A + (size_t)gArow * K + acol;
    const float* Bptr = W + (size_t)brow * F + bn * 128 + bcol;

    for (int k0 = 0; k0 < K; k0 += 8) {
        float4 av = make_float4(0.f, 0.f, 0.f, 0.f);
        if (gArow < M) av = *(const float4*)(Aptr + k0);
        As[acol + 0][arow] = av.x;
        As[acol + 1][arow] = av.y;
        As[acol + 2][arow] = av.z;
        As[acol + 3][arow] = av.w;
        float4 bv = *(const float4*)(Bptr + (size_t)k0 * F);
        *(float4*)&Bs[brow][bcol] = bv;
        __syncthreads();
#pragma unroll
        for (int k = 0; k < 8; k++) {
            float4 a0 = *(const float4*)&As[k][ty * 4];
            float4 a1 = *(const float4*)&As[k][64 + ty * 4];
            float4 b0v = *(const float4*)&Bs[k][tx * 4];
            float4 b1v = *(const float4*)&Bs[k][64 + tx * 4];
            float ar[8] = {a0.x, a0.y, a0.z, a0.w, a1.x, a1.y, a1.z, a1.w};
            float br[8] = {b0v.x, b0v.y, b0v.z, b0v.w, b1v.x, b1v.y, b1v.z, b1v.w};
#pragma unroll
            for (int i = 0; i < 8; i++)
#pragma unroll
                for (int j = 0; j < 8; j++) acc[i][j] = fmaf(ar[i], br[j], acc[i][j]);
        }
        __syncthreads();
    }
#pragma unroll
    for (int iq = 0; iq < 2; iq++)
#pragma unroll
        for (int ii = 0; ii < 4; ii++) {
            int r = bm * 128 + iq * 64 + ty * 4 + ii;
            if (r >= M) continue;
#pragma unroll
            for (int jq = 0; jq < 2; jq++) {
                int c = bn * 128 + jq * 64 + tx * 4;
                float* op = outp + (size_t)r * F + c;
                op[0] = acc[iq * 4 + ii][jq * 4 + 0] + b[c + 0];
                op[1] = acc[iq * 4 + ii][jq * 4 + 1] + b[c + 1];
                op[2] = acc[iq * 4 + ii][jq * 4 + 2] + b[c + 2];
                op[3] = acc[iq * 4 + ii][jq * 4 + 3] + b[c + 3];
            }
        }
}

// ---------------- CSR dst-side score: warp per node, q cached in registers ----------------
template <int H, int C>
__global__ void k_alphaC(const int* __restrict__ src,
                         const float* __restrict__ q, const float* __restrict__ k,
                         int n, float scale) {
    constexpr int F = H * C;
    constexpr int T = F / 128;   // float4 per lane
    int node = (blockIdx.x * blockDim.x + threadIdx.x) >> 5;
    int lane = threadIdx.x & 31;
    if (node >= n) return;
    int s0 = g_rowptr[node], s1 = g_rowptr[node + 1];
    if (s0 == s1) return;

    float4 qr[T];
    const float4* qp = (const float4*)(q + (size_t)node * F);
#pragma unroll
    for (int t = 0; t < T; t++) qr[t] = qp[lane + 32 * t];

    for (int j = s0; j < s1; j++) {
        int e = g_perm[j];
        const float4* kp = (const float4*)(k + (size_t)src[e] * F);
        float acc[H];
#pragma unroll
        for (int h = 0; h < H; h++) acc[h] = 0.f;
#pragma unroll
        for (int t = 0; t < T; t++) {
            float4 a = qr[t], b = kp[lane + 32 * t];
            float d = a.x * b.x + a.y * b.y + a.z * b.z + a.w * b.w;
            if constexpr (C == 128) {
                acc[t] += d;
            } else {
                if (lane < 16) acc[2 * t] += d;
                else acc[2 * t + 1] += d;
            }
        }
#pragma unroll
        for (int h = 0; h < H; h++) {
            float v = acc[h];
#pragma unroll
            for (int o = 16; o; o >>= 1) v += __shfl_xor_sync(0xffffffffu, v, o);
            if (lane == 0) g_alpha[(size_t)e * H + h] = v * scale;
        }
    }
}

// ---------------- CSR warp-per-node: softmax + aggregate + skip + LN + ELU ----------------
template <int H, int C>
__global__ void k_aggC(const int* __restrict__ src,
                       const float* __restrict__ v, const float* __restrict__ sskip,
                       const float* __restrict__ lng, const float* __restrict__ lnb,
                       float* __restrict__ outp, int n) {
    constexpr int F = H * C, CC = F / 32;
    int node = (blockIdx.x * blockDim.x + threadIdx.x) >> 5;
    int lane = threadIdx.x & 31;
    if (node >= n) return;
    int s0 = g_rowptr[node], s1 = g_rowptr[node + 1], deg = s1 - s0;

    float m[H], dn[H];
#pragma unroll
    for (int h = 0; h < H; h++) {
        float mv = -INFINITY;
        for (int j = lane; j < deg; j += 32)
            mv = fmaxf(mv, g_alpha[(size_t)g_perm[s0 + j] * H + h]);
#pragma unroll
        for (int o = 16; o; o >>= 1) mv = fmaxf(mv, __shfl_xor_sync(0xffffffffu, mv, o));
        m[h] = mv;
        float sv = 0.f;
        for (int j = lane; j < deg; j += 32)
            sv += expf(g_alpha[(size_t)g_perm[s0 + j] * H + h] - mv);
#pragma unroll
        for (int o = 16; o; o >>= 1) sv += __shfl_xor_sync(0xffffffffu, sv, o);
        dn[h] = 1.f / (sv + 1e-16f);
    }

    float acc[CC];
#pragma unroll
    for (int cc = 0; cc < CC; cc++) acc[cc] = 0.f;

    for (int j = 0; j < deg; j++) {
        int e = g_perm[s0 + j];
        int sv = src[e];
        float w[H];
#pragma unroll
        for (int h = 0; h < H; h++)
            w[h] = expf(g_alpha[(size_t)e * H + h] - m[h]) * dn[h];
        const float* vr = v + (size_t)sv * F;
#pragma unroll
        for (int cc = 0; cc < CC; cc++)
            acc[cc] = fmaf(w[(32 * cc) / C], vr[lane + 32 * cc], acc[cc]);
    }
    const float* sr = sskip + (size_t)node * F;
#pragma unroll
    for (int cc = 0; cc < CC; cc++) acc[cc] += sr[lane + 32 * cc];

    float s = 0.f;
#pragma unroll
    for (int cc = 0; cc < CC; cc++) s += acc[cc];
#pragma unroll
    for (int o = 16; o; o >>= 1) s += __shfl_xor_sync(0xffffffffu, s, o);
    float mean = s / (float)F;
    float vs = 0.f;
#pragma unroll
    for (int cc = 0; cc < CC; cc++) {
        float d = acc[cc] - mean;
        vs = fmaf(d, d, vs);
    }
#pragma unroll
    for (int o = 16; o; o >>= 1) vs += __shfl_xor_sync(0xffffffffu, vs, o);
    float r = rsqrtf(vs / (float)F + 1e-5f);
#pragma unroll
    for (int cc = 0; cc < CC; cc++) {
        int ch = lane + 32 * cc;
        float t = (acc[cc] - mean) * r * lng[ch] + lnb[ch];
        outp[(size_t)node * F + ch] = t > 0.f ? t : expm1f(t);
    }
}

// ---------------- layer 3: fused projection, warp per node (K=256 -> 8 outputs) ----------------
__global__ void k_gemm3f(const float* __restrict__ X,
                         const float* __restrict__ Wq, const float* __restrict__ bq,
                         const float* __restrict__ Wk, const float* __restrict__ bk,
                         const float* __restrict__ Wv, const float* __restrict__ bv,
                         const float* __restrict__ Ws, const float* __restrict__ bs,
                         float* __restrict__ q, float* __restrict__ k,
                         float* __restrict__ v, float* __restrict__ sOut, int n) {
    int node = (blockIdx.x * blockDim.x + threadIdx.x) >> 5;
    int lane = threadIdx.x & 31;
    if (node >= n) return;
    const float* x = X + (size_t)node * 256;
    float a[8];
#pragma unroll
    for (int i = 0; i < 8; i++) a[i] = 0.f;
#pragma unroll
    for (int t = 0; t < 8; t++) {
        int i = lane + 32 * t;
        float xv = x[i];
        a[0] = fmaf(xv, Wq[i * 2], a[0]);
        a[1] = fmaf(xv, Wq[i * 2 + 1], a[1]);
        a[2] = fmaf(xv, Wk[i * 2], a[2]);
        a[3] = fmaf(xv, Wk[i * 2 + 1], a[3]);
        a[4] = fmaf(xv, Wv[i * 2], a[4]);
        a[5] = fmaf(xv, Wv[i * 2 + 1], a[5]);
        a[6] = fmaf(xv, Ws[i * 2], a[6]);
        a[7] = fmaf(xv, Ws[i * 2 + 1], a[7]);
    }
#pragma unroll
    for (int i = 0; i < 8; i++) {
#pragma unroll
        for (int o = 16; o; o >>= 1) a[i] += __shfl_xor_sync(0xffffffffu, a[i], o);
    }
    if (lane == 0) {
        q[(size_t)node * 2 + 0] = a[0] + bq[0];
        q[(size_t)node * 2 + 1] = a[1] + bq[1];
        k[(size_t)node * 2 + 0] = a[2] + bk[0];
        k[(size_t)node * 2 + 1] = a[3] + bk[1];
        v[(size_t)node * 2 + 0] = a[4] + bv[0];
        v[(size_t)node * 2 + 1] = a[5] + bv[1];
        sOut[(size_t)node * 2 + 0] = a[6] + bs[0];
        sOut[(size_t)node * 2 + 1] = a[7] + bs[1];
    }
}

// ---------------- layer-3 score: thread-per-edge (C=2) ----------------
__global__ void k_alpha3(const int* __restrict__ src, const int* __restrict__ dst,
                         const float* __restrict__ q, const float* __restrict__ k,
                         int E, float scale) {
    int e = blockIdx.x * blockDim.x + threadIdx.x;
    if (e >= E) return;
    const float* qp = q + (size_t)dst[e] * 2;
    const float* kp = k + (size_t)src[e] * 2;
    g_alpha[e] = (qp[0] * kp[0] + qp[1] * kp[1]) * scale;
}

// ---------------- layer 3 CSR finalize ----------------
__global__ void k_final3(const int* __restrict__ src,
                         const float* __restrict__ v2, const float* __restrict__ s3,
                         float* __restrict__ out, int n) {
    int i = blockIdx.x * blockDim.x + threadIdx.x;
    if (i >= n) return;
    int s0 = g_rowptr[i], s1 = g_rowptr[i + 1];
    float m = -INFINITY;
    for (int j = s0; j < s1; j++) m = fmaxf(m, g_alpha[g_perm[j]]);
    float a0 = 0.f, a1 = 0.f;
    if (s1 > s0) {
        float dnm = 0.f;
        for (int j = s0; j < s1; j++) dnm += expf(g_alpha[g_perm[j]] - m);
        float inv = 1.f / (dnm + 1e-16f);
        for (int j = s0; j < s1; j++) {
            int e = g_perm[j];
            float w = expf(g_alpha[e] - m) * inv;
            const float* vr = v2 + (size_t)src[e] * 2;
            a0 = fmaf(w, vr[0], a0);
            a1 = fmaf(w, vr[1], a1);
        }
    }
    float h0 = a0 + s3[(size_t)i * 2 + 0];
    float h1 = a1 + s3[(size_t)i * 2 + 1];
    float mx = fmaxf(h0, h1);
    float lse = mx + logf(expf(h0 - mx) + expf(h1 - mx));
    out[2 * i + 0] = h0 - lse;
    out[2 * i + 1] = h1 - lse;
}

// ---------------- launch ----------------
static inline int cdiv(int a, int b) { return (a + b - 1) / b; }

extern "C" void kernel_launch(void* const* d_in, const int* in_sizes, int n_in,
                              void* d_out, int out_size) {
    const float* x = (const float*)d_in[0];
    const int* ei = (const int*)d_in[1];
    const int N = in_sizes[0] / 128;
    const int E = in_sizes[1] / 2;
    const int* src = ei;
    const int* dst = ei + E;

    const float *Wq1 = (const float*)d_in[2],  *bq1 = (const float*)d_in[3];
    const float *Wk1 = (const float*)d_in[4],  *bk1 = (const float*)d_in[5];
    const float *Wv1 = (const float*)d_in[6],  *bv1 = (const float*)d_in[7];
    const float *Ws1 = (const float*)d_in[8],  *bs1 = (const float*)d_in[9];
    const float *Wq2 = (const float*)d_in[10], *bq2 = (const float*)d_in[11];
    const float *Wk2 = (const float*)d_in[12], *bk2 = (const float*)d_in[13];
    const float *Wv2 = (const float*)d_in[14], *bv2 = (const float*)d_in[15];
    const float *Ws2 = (const float*)d_in[16], *bs2 = (const float*)d_in[17];
    const float *Wq3 = (const float*)d_in[18], *bq3 = (const float*)d_in[19];
    const float *Wk3 = (const float*)d_in[20], *bk3 = (const float*)d_in[21];
    const float *Wv3 = (const float*)d_in[22], *bv3 = (const float*)d_in[23];
    const float *Ws3 = (const float*)d_in[24], *bs3 = (const float*)d_in[25];
    const float *ln1g = (const float*)d_in[26], *ln1b = (const float*)d_in[27];
    const float *ln2g = (const float*)d_in[28], *ln2b = (const float*)d_in[29];
    float* out = (float*)d_out;

    static float* yb = nullptr;
    if (!yb) { void* p; cudaGetSymbolAddress(&p, g_y); yb = (float*)p; }
    float* q = yb;
    float* k = yb + (size_t)NN * 512;
    float* v = yb + (size_t)NN * 1024;
    float* sOut = yb + (size_t)NN * 1536;
    static float* hb = nullptr;
    if (!hb) { void* p; cudaGetSymbolAddress(&p, g_h); hb = (float*)p; }

    const int TB = 256;

    // CSR build by dst (used by all 3 layers)
    int n1 = N + 1;
    int nch = cdiv(n1, 256);
    k_zero_rowptr<<<cdiv(n1, TB), TB>>>(n1);
    k_count<<<cdiv(E, TB), TB>>>(dst, E);
    k_block_sums<<<nch, 256>>>(n1);
    k_scan_chunks<<<1, 32>>>(nch);
    k_block_scan<<<nch, 256>>>(n1);
    k_cursor<<<cdiv(N, TB), TB>>>(N);
    k_scatter<<<cdiv(E, TB), TB>>>(dst, E);

    // ================= layer 1: K=128, F=512, H=4, C=128 =================
    {
        int K = 128, F = 512;
        dim3 grid(4 * F / 128, cdiv(N, 128));
        k_sgemm4<<<grid, 256>>>(x, Wq1, bq1, q, Wk1, bk1, k, Wv1, bv1, v, Ws1, bs1, sOut, N, K, F);
        k_alphaC<4, 128><<<cdiv(N * 32, TB), TB>>>(src, q, k, N, 0.08838834764831845f);
        k_aggC<4, 128><<<cdiv(N * 32, TB), TB>>>(src, v, sOut, ln1g, ln1b, hb, N);
    }
    // ================= layer 2: K=512, F=256, H=4, C=64 =================
    {
        int K = 512, F = 256;
        dim3 grid(4 * F / 128, cdiv(N, 128));
        k_sgemm4<<<grid, 256>>>(hb, Wq2, bq2, q, Wk2, bk2, k, Wv2, bv2, v, Ws2, bs2, sOut, N, K, F);
        k_alphaC<4, 64><<<cdiv(N * 32, TB), TB>>>(src, q, k, N, 0.125f);
        k_aggC<4, 64><<<cdiv(N * 32, TB), TB>>>(src, v, sOut, ln2g, ln2b, hb, N);
    }
    // ================= layer 3: K=256, F=2, H=1, C=2 =================
    {
        k_gemm3f<<<cdiv(N * 32, TB), TB>>>(hb, Wq3, bq3, Wk3, bk3, Wv3, bv3, Ws3, bs3,
                                           q, k, v, sOut, N);
        k_alpha3<<<cdiv(E, TB), TB>>>(src, dst, q, k, E, 0.7071067811865475f);
        k_final3<<<cdiv(N, TB), TB>>>(src, v, sOut, out, N);
    }
}

// round 9
// speedup vs baseline: 7.5014x; 1.2968x over previous
#include <cuda_runtime.h>
#include <cstdint>
#include <stdint.h>
#include <math.h>

#define NN 50000
#define EE 400000

// ---------------- scratch (device globals) ----------------
__device__ float g_y[(size_t)NN * 2048];     // q|k|v|s slices, each NN*512
__device__ float g_h[(size_t)NN * 512];
__device__ float g_alpha[(size_t)EE * 4];
__device__ int   g_rowptr[NN + 1];
__device__ int   g_cursor[NN];
__device__ int   g_perm[EE];
__device__ int   g_chunksum[256];

// ---------------- CSR build (by dst) ----------------
__global__ void k_zero_rowptr(int n) {
    int i = blockIdx.x * blockDim.x + threadIdx.x;
    if (i < n) g_rowptr[i] = 0;
}
__global__ void k_count(const int* __restrict__ dst, int E) {
    int e = blockIdx.x * blockDim.x + threadIdx.x;
    if (e < E) atomicAdd(&g_rowptr[dst[e] + 1], 1);
}
__global__ void k_block_sums(int n) {
    __shared__ int sh[256];
    int i = blockIdx.x * 256 + threadIdx.x;
    sh[threadIdx.x] = (i < n) ? g_rowptr[i] : 0;
    __syncthreads();
    for (int o = 128; o > 0; o >>= 1) {
        if (threadIdx.x < o) sh[threadIdx.x] += sh[threadIdx.x + o];
        __syncthreads();
    }
    if (threadIdx.x == 0) g_chunksum[blockIdx.x] = sh[0];
}
__global__ void k_scan_chunks(int nch) {
    if (threadIdx.x == 0 && blockIdx.x == 0) {
        int running = 0;
        for (int i = 0; i < nch; i++) {
            int t = g_chunksum[i];
            g_chunksum[i] = running;
            running += t;
        }
    }
}
__global__ void k_block_scan(int n) {
    __shared__ int sh[256];
    int i = blockIdx.x * 256 + threadIdx.x;
    int t = threadIdx.x;
    sh[t] = (i < n) ? g_rowptr[i] : 0;
    __syncthreads();
    for (int o = 1; o < 256; o <<= 1) {
        int v = sh[t];
        int u = (t >= o) ? sh[t - o] : 0;
        __syncthreads();
        sh[t] = v + u;
        __syncthreads();
    }
    if (i < n) g_rowptr[i] = sh[t] + g_chunksum[blockIdx.x];
}
__global__ void k_cursor(int n) {
    int i = blockIdx.x * blockDim.x + threadIdx.x;
    if (i < n) g_cursor[i] = g_rowptr[i];
}
__global__ void k_scatter(const int* __restrict__ dst, int E) {
    int e = blockIdx.x * blockDim.x + threadIdx.x;
    if (e < E) {
        int p = atomicAdd(&g_cursor[dst[e]], 1);
        g_perm[p] = e;
    }
}

// ---------------- TF32x3 tensor-core GEMM ----------------
__device__ __forceinline__ uint32_t f2tf(float x) {
    uint32_t r;
    asm("cvt.rna.tf32.f32 %0, %1;" : "=r"(r) : "f"(x));
    return r;
}
__device__ __forceinline__ void mma_tf32(float* c, const uint32_t* a, const uint32_t* b) {
    asm volatile(
        "mma.sync.aligned.m16n8k8.row.col.f32.tf32.tf32.f32 "
        "{%0,%1,%2,%3}, {%4,%5,%6,%7}, {%8,%9}, {%0,%1,%2,%3};"
        : "+f"(c[0]), "+f"(c[1]), "+f"(c[2]), "+f"(c[3])
        : "r"(a[0]), "r"(a[1]), "r"(a[2]), "r"(a[3]), "r"(b[0]), "r"(b[1]));
}

#define AST 36     // A smem stride [m][k], 128 rows x 32 k
#define BST 136    // B smem stride [k][n], 32 k x 128 n
#define MMA_SMEM ((2 * 128 * AST + 2 * 32 * BST) * 4)   // 71680 B

// fused 4-way: {o0..o3}[M,F] = A[M,K] @ W{0..3}[K,F] + b{0..3}; tf32x3 compensated.
// grid.x = 4*(F/128), grid.y = ceil(M/128), 256 threads.
__global__ void __launch_bounds__(256) k_mma4(const float* __restrict__ Ag,
                                              const float* __restrict__ W0, const float* __restrict__ b0, float* __restrict__ o0,
                                              const float* __restrict__ W1, const float* __restrict__ b1, float* __restrict__ o1,
                                              const float* __restrict__ W2, const float* __restrict__ b2, float* __restrict__ o2,
                                              const float* __restrict__ W3, const float* __restrict__ b3, float* __restrict__ o3,
                                              int M, int K, int F) {
    extern __shared__ float sm[];
    float* As_hi = sm;                       // [128][AST]
    float* As_lo = As_hi + 128 * AST;
    float* Bs_hi = As_lo + 128 * AST;        // [32][BST]
    float* Bs_lo = Bs_hi + 32 * BST;

    int tid = threadIdx.x;
    int warp = tid >> 5, lane = tid & 31;
    int wm = warp >> 2;        // 0..1 : 64-row slab
    int wn = warp & 3;         // 0..3 : 32-col slab
    int gid = lane >> 2;       // 0..7
    int l4 = lane & 3;         // 0..3

    int nb = F / 128;
    int bsel = blockIdx.x / nb;
    int bn = blockIdx.x % nb;
    int bm = blockIdx.y;
    const float* W = bsel == 0 ? W0 : bsel == 1 ? W1 : bsel == 2 ? W2 : W3;
    const float* bias = bsel == 0 ? b0 : bsel == 1 ? b1 : bsel == 2 ? b2 : b3;
    float* outp = bsel == 0 ? o0 : bsel == 1 ? o1 : bsel == 2 ? o2 : o3;

    float acc[4][4][4];
#pragma unroll
    for (int i = 0; i < 4; i++)
#pragma unroll
        for (int j = 0; j < 4; j++)
#pragma unroll
            for (int r = 0; r < 4; r++) acc[i][j][r] = 0.f;

    for (int k0 = 0; k0 < K; k0 += 32) {
        __syncthreads();
        // ---- load A tile [128 m][32 k], split hi/lo ----
#pragma unroll
        for (int i = 0; i < 4; i++) {
            int r = (tid >> 3) + i * 32;
            int fc = (tid & 7) * 4;
            int gr = bm * 128 + r;
            float4 v = make_float4(0.f, 0.f, 0.f, 0.f);
            if (gr < M) v = *(const float4*)(Ag + (size_t)gr * K + k0 + fc);
            float4 h, l;
            h.x = __uint_as_float(f2tf(v.x)); l.x = __uint_as_float(f2tf(v.x - h.x));
            h.y = __uint_as_float(f2tf(v.y)); l.y = __uint_as_float(f2tf(v.y - h.y));
            h.z = __uint_as_float(f2tf(v.z)); l.z = __uint_as_float(f2tf(v.z - h.z));
            h.w = __uint_as_float(f2tf(v.w)); l.w = __uint_as_float(f2tf(v.w - h.w));
            *(float4*)(As_hi + r * AST + fc) = h;
            *(float4*)(As_lo + r * AST + fc) = l;
        }
        // ---- load B tile [32 k][128 n], split hi/lo ----
        {
            int kk = tid >> 3;
            const float* Wrow = W + (size_t)(k0 + kk) * F + bn * 128;
#pragma unroll
            for (int i = 0; i < 4; i++) {
                int n = (tid & 7) * 4 + i * 32;
                float4 v = *(const float4*)(Wrow + n);
                float4 h, l;
                h.x = __uint_as_float(f2tf(v.x)); l.x = __uint_as_float(f2tf(v.x - h.x));
                h.y = __uint_as_float(f2tf(v.y)); l.y = __uint_as_float(f2tf(v.y - h.y));
                h.z = __uint_as_float(f2tf(v.z)); l.z = __uint_as_float(f2tf(v.z - h.z));
                h.w = __uint_as_float(f2tf(v.w)); l.w = __uint_as_float(f2tf(v.w - h.w));
                *(float4*)(Bs_hi + kk * BST + n) = h;
                *(float4*)(Bs_lo + kk * BST + n) = l;
            }
        }
        __syncthreads();

#pragma unroll
        for (int ks = 0; ks < 32; ks += 8) {
            uint32_t ah[4][4], al[4][4], bh[4][2], bl[4][2];
#pragma unroll
            for (int tm = 0; tm < 4; tm++) {
                int m0 = wm * 64 + tm * 16 + gid;
                const float* ph = As_hi + m0 * AST + ks + l4;
                const float* pl = As_lo + m0 * AST + ks + l4;
                ah[tm][0] = __float_as_uint(ph[0]);
                ah[tm][1] = __float_as_uint(ph[8 * AST]);
                ah[tm][2] = __float_as_uint(ph[4]);
                ah[tm][3] = __float_as_uint(ph[8 * AST + 4]);
                al[tm][0] = __float_as_uint(pl[0]);
                al[tm][1] = __float_as_uint(pl[8 * AST]);
                al[tm][2] = __float_as_uint(pl[4]);
                al[tm][3] = __float_as_uint(pl[8 * AST + 4]);
            }
#pragma unroll
            for (int tn = 0; tn < 4; tn++) {
                int n0 = wn * 32 + tn * 8 + gid;
                const float* ph = Bs_hi + (ks + l4) * BST + n0;
                const float* pl = Bs_lo + (ks + l4) * BST + n0;
                bh[tn][0] = __float_as_uint(ph[0]);
                bh[tn][1] = __float_as_uint(ph[4 * BST]);
                bl[tn][0] = __float_as_uint(pl[0]);
                bl[tn][1] = __float_as_uint(pl[4 * BST]);
            }
#pragma unroll
            for (int tm = 0; tm < 4; tm++)
#pragma unroll
                for (int tn = 0; tn < 4; tn++) {
                    mma_tf32(acc[tm][tn], ah[tm], bh[tn]);
                    mma_tf32(acc[tm][tn], ah[tm], bl[tn]);
                    mma_tf32(acc[tm][tn], al[tm], bh[tn]);
                }
        }
    }

    // ---- epilogue ----
#pragma unroll
    for (int tm = 0; tm < 4; tm++) {
        int r0 = bm * 128 + wm * 64 + tm * 16 + gid;
        int r1 = r0 + 8;
#pragma unroll
        for (int tn = 0; tn < 4; tn++) {
            int c = bn * 128 + wn * 32 + tn * 8 + l4 * 2;
            if (r0 < M) {
                outp[(size_t)r0 * F + c] = acc[tm][tn][0] + bias[c];
                outp[(size_t)r0 * F + c + 1] = acc[tm][tn][1] + bias[c + 1];
            }
            if (r1 < M) {
                outp[(size_t)r1 * F + c] = acc[tm][tn][2] + bias[c];
                outp[(size_t)r1 * F + c + 1] = acc[tm][tn][3] + bias[c + 1];
            }
        }
    }
}

// ---------------- CSR dst-side score: warp per node, q cached in registers ----------------
template <int H, int C>
__global__ void k_alphaC(const int* __restrict__ src,
                         const float* __restrict__ q, const float* __restrict__ k,
                         int n, float scale) {
    constexpr int F = H * C;
    constexpr int T = F / 128;
    int node = (blockIdx.x * blockDim.x + threadIdx.x) >> 5;
    int lane = threadIdx.x & 31;
    if (node >= n) return;
    int s0 = g_rowptr[node], s1 = g_rowptr[node + 1];
    if (s0 == s1) return;

    float4 qr[T];
    const float4* qp = (const float4*)(q + (size_t)node * F);
#pragma unroll
    for (int t = 0; t < T; t++) qr[t] = qp[lane + 32 * t];

    for (int j = s0; j < s1; j++) {
        int e = g_perm[j];
        const float4* kp = (const float4*)(k + (size_t)src[e] * F);
        float acc[H];
#pragma unroll
        for (int h = 0; h < H; h++) acc[h] = 0.f;
#pragma unroll
        for (int t = 0; t < T; t++) {
            float4 a = qr[t], b = kp[lane + 32 * t];
            float d = a.x * b.x + a.y * b.y + a.z * b.z + a.w * b.w;
            if constexpr (C == 128) {
                acc[t] += d;
            } else {
                if (lane < 16) acc[2 * t] += d;
                else acc[2 * t + 1] += d;
            }
        }
#pragma unroll
        for (int h = 0; h < H; h++) {
            float v = acc[h];
#pragma unroll
            for (int o = 16; o; o >>= 1) v += __shfl_xor_sync(0xffffffffu, v, o);
            if (lane == 0) g_alpha[(size_t)e * H + h] = v * scale;
        }
    }
}

// ---------------- CSR warp-per-node: softmax + aggregate + skip + LN + ELU ----------------
template <int H, int C>
__global__ void k_aggC(const int* __restrict__ src,
                       const float* __restrict__ v, const float* __restrict__ sskip,
                       const float* __restrict__ lng, const float* __restrict__ lnb,
                       float* __restrict__ outp, int n) {
    constexpr int F = H * C, CC = F / 32;
    int node = (blockIdx.x * blockDim.x + threadIdx.x) >> 5;
    int lane = threadIdx.x & 31;
    if (node >= n) return;
    int s0 = g_rowptr[node], s1 = g_rowptr[node + 1], deg = s1 - s0;

    float m[H], dn[H];
#pragma unroll
    for (int h = 0; h < H; h++) {
        float mv = -INFINITY;
        for (int j = lane; j < deg; j += 32)
            mv = fmaxf(mv, g_alpha[(size_t)g_perm[s0 + j] * H + h]);
#pragma unroll
        for (int o = 16; o; o >>= 1) mv = fmaxf(mv, __shfl_xor_sync(0xffffffffu, mv, o));
        m[h] = mv;
        float sv = 0.f;
        for (int j = lane; j < deg; j += 32)
            sv += expf(g_alpha[(size_t)g_perm[s0 + j] * H + h] - mv);
#pragma unroll
        for (int o = 16; o; o >>= 1) sv += __shfl_xor_sync(0xffffffffu, sv, o);
        dn[h] = 1.f / (sv + 1e-16f);
    }

    float acc[CC];
#pragma unroll
    for (int cc = 0; cc < CC; cc++) acc[cc] = 0.f;

    for (int j = 0; j < deg; j++) {
        int e = g_perm[s0 + j];
        int sv = src[e];
        float w[H];
#pragma unroll
        for (int h = 0; h < H; h++)
            w[h] = expf(g_alpha[(size_t)e * H + h] - m[h]) * dn[h];
        const float* vr = v + (size_t)sv * F;
#pragma unroll
        for (int cc = 0; cc < CC; cc++)
            acc[cc] = fmaf(w[(32 * cc) / C], vr[lane + 32 * cc], acc[cc]);
    }
    const float* sr = sskip + (size_t)node * F;
#pragma unroll
    for (int cc = 0; cc < CC; cc++) acc[cc] += sr[lane + 32 * cc];

    float s = 0.f;
#pragma unroll
    for (int cc = 0; cc < CC; cc++) s += acc[cc];
#pragma unroll
    for (int o = 16; o; o >>= 1) s += __shfl_xor_sync(0xffffffffu, s, o);
    float mean = s / (float)F;
    float vs = 0.f;
#pragma unroll
    for (int cc = 0; cc < CC; cc++) {
        float d = acc[cc] - mean;
        vs = fmaf(d, d, vs);
    }
#pragma unroll
    for (int o = 16; o; o >>= 1) vs += __shfl_xor_sync(0xffffffffu, vs, o);
    float r = rsqrtf(vs / (float)F + 1e-5f);
#pragma unroll
    for (int cc = 0; cc < CC; cc++) {
        int ch = lane + 32 * cc;
        float t = (acc[cc] - mean) * r * lng[ch] + lnb[ch];
        outp[(size_t)node * F + ch] = t > 0.f ? t : expm1f(t);
    }
}

// ---------------- layer 3: fused projection, warp per node (K=256 -> 8 outputs) ----------------
__global__ void k_gemm3f(const float* __restrict__ X,
                         const float* __restrict__ Wq, const float* __restrict__ bq,
                         const float* __restrict__ Wk, const float* __restrict__ bk,
                         const float* __restrict__ Wv, const float* __restrict__ bv,
                         const float* __restrict__ Ws, const float* __restrict__ bs,
                         float* __restrict__ q, float* __restrict__ k,
                         float* __restrict__ v, float* __restrict__ sOut, int n) {
    int node = (blockIdx.x * blockDim.x + threadIdx.x) >> 5;
    int lane = threadIdx.x & 31;
    if (node >= n) return;
    const float* x = X + (size_t)node * 256;
    float a[8];
#pragma unroll
    for (int i = 0; i < 8; i++) a[i] = 0.f;
#pragma unroll
    for (int t = 0; t < 8; t++) {
        int i = lane + 32 * t;
        float xv = x[i];
        a[0] = fmaf(xv, Wq[i * 2], a[0]);
        a[1] = fmaf(xv, Wq[i * 2 + 1], a[1]);
        a[2] = fmaf(xv, Wk[i * 2], a[2]);
        a[3] = fmaf(xv, Wk[i * 2 + 1], a[3]);
        a[4] = fmaf(xv, Wv[i * 2], a[4]);
        a[5] = fmaf(xv, Wv[i * 2 + 1], a[5]);
        a[6] = fmaf(xv, Ws[i * 2], a[6]);
        a[7] = fmaf(xv, Ws[i * 2 + 1], a[7]);
    }
#pragma unroll
    for (int i = 0; i < 8; i++) {
#pragma unroll
        for (int o = 16; o; o >>= 1) a[i] += __shfl_xor_sync(0xffffffffu, a[i], o);
    }
    if (lane == 0) {
        q[(size_t)node * 2 + 0] = a[0] + bq[0];
        q[(size_t)node * 2 + 1] = a[1] + bq[1];
        k[(size_t)node * 2 + 0] = a[2] + bk[0];
        k[(size_t)node * 2 + 1] = a[3] + bk[1];
        v[(size_t)node * 2 + 0] = a[4] + bv[0];
        v[(size_t)node * 2 + 1] = a[5] + bv[1];
        sOut[(size_t)node * 2 + 0] = a[6] + bs[0];
        sOut[(size_t)node * 2 + 1] = a[7] + bs[1];
    }
}

// ---------------- layer-3 score: thread-per-edge (C=2) ----------------
__global__ void k_alpha3(const int* __restrict__ src, const int* __restrict__ dst,
                         const float* __restrict__ q, const float* __restrict__ k,
                         int E, float scale) {
    int e = blockIdx.x * blockDim.x + threadIdx.x;
    if (e >= E) return;
    const float* qp = q + (size_t)dst[e] * 2;
    const float* kp = k + (size_t)src[e] * 2;
    g_alpha[e] = (qp[0] * kp[0] + qp[1] * kp[1]) * scale;
}

// ---------------- layer 3 CSR finalize ----------------
__global__ void k_final3(const int* __restrict__ src,
                         const float* __restrict__ v2, const float* __restrict__ s3,
                         float* __restrict__ out, int n) {
    int i = blockIdx.x * blockDim.x + threadIdx.x;
    if (i >= n) return;
    int s0 = g_rowptr[i], s1 = g_rowptr[i + 1];
    float m = -INFINITY;
    for (int j = s0; j < s1; j++) m = fmaxf(m, g_alpha[g_perm[j]]);
    float a0 = 0.f, a1 = 0.f;
    if (s1 > s0) {
        float dnm = 0.f;
        for (int j = s0; j < s1; j++) dnm += expf(g_alpha[g_perm[j]] - m);
        float inv = 1.f / (dnm + 1e-16f);
        for (int j = s0; j < s1; j++) {
            int e = g_perm[j];
            float w = expf(g_alpha[e] - m) * inv;
            const float* vr = v2 + (size_t)src[e] * 2;
            a0 = fmaf(w, vr[0], a0);
            a1 = fmaf(w, vr[1], a1);
        }
    }
    float h0 = a0 + s3[(size_t)i * 2 + 0];
    float h1 = a1 + s3[(size_t)i * 2 + 1];
    float mx = fmaxf(h0, h1);
    float lse = mx + logf(expf(h0 - mx) + expf(h1 - mx));
    out[2 * i + 0] = h0 - lse;
    out[2 * i + 1] = h1 - lse;
}

// ---------------- launch ----------------
static inline int cdiv(int a, int b) { return (a + b - 1) / b; }

extern "C" void kernel_launch(void* const* d_in, const int* in_sizes, int n_in,
                              void* d_out, int out_size) {
    const float* x = (const float*)d_in[0];
    const int* ei = (const int*)d_in[1];
    const int N = in_sizes[0] / 128;
    const int E = in_sizes[1] / 2;
    const int* src = ei;
    const int* dst = ei + E;

    const float *Wq1 = (const float*)d_in[2],  *bq1 = (const float*)d_in[3];
    const float *Wk1 = (const float*)d_in[4],  *bk1 = (const float*)d_in[5];
    const float *Wv1 = (const float*)d_in[6],  *bv1 = (const float*)d_in[7];
    const float *Ws1 = (const float*)d_in[8],  *bs1 = (const float*)d_in[9];
    const float *Wq2 = (const float*)d_in[10], *bq2 = (const float*)d_in[11];
    const float *Wk2 = (const float*)d_in[12], *bk2 = (const float*)d_in[13];
    const float *Wv2 = (const float*)d_in[14], *bv2 = (const float*)d_in[15];
    const float *Ws2 = (const float*)d_in[16], *bs2 = (const float*)d_in[17];
    const float *Wq3 = (const float*)d_in[18], *bq3 = (const float*)d_in[19];
    const float *Wk3 = (const float*)d_in[20], *bk3 = (const float*)d_in[21];
    const float *Wv3 = (const float*)d_in[22], *bv3 = (const float*)d_in[23];
    const float *Ws3 = (const float*)d_in[24], *bs3 = (const float*)d_in[25];
    const float *ln1g = (const float*)d_in[26], *ln1b = (const float*)d_in[27];
    const float *ln2g = (const float*)d_in[28], *ln2b = (const float*)d_in[29];
    float* out = (float*)d_out;

    static float* yb = nullptr;
    if (!yb) { void* p; cudaGetSymbolAddress(&p, g_y); yb = (float*)p; }
    float* q = yb;
    float* k = yb + (size_t)NN * 512;
    float* v = yb + (size_t)NN * 1024;
    float* sOut = yb + (size_t)NN * 1536;
    static float* hb = nullptr;
    if (!hb) { void* p; cudaGetSymbolAddress(&p, g_h); hb = (float*)p; }

    static bool cfg = false;
    if (!cfg) {
        cudaFuncSetAttribute(k_mma4, cudaFuncAttributeMaxDynamicSharedMemorySize, MMA_SMEM);
        cfg = true;
    }

    const int TB = 256;

    // CSR build by dst (used by all 3 layers)
    int n1 = N + 1;
    int nch = cdiv(n1, 256);
    k_zero_rowptr<<<cdiv(n1, TB), TB>>>(n1);
    k_count<<<cdiv(E, TB), TB>>>(dst, E);
    k_block_sums<<<nch, 256>>>(n1);
    k_scan_chunks<<<1, 32>>>(nch);
    k_block_scan<<<nch, 256>>>(n1);
    k_cursor<<<cdiv(N, TB), TB>>>(N);
    k_scatter<<<cdiv(E, TB), TB>>>(dst, E);

    // ================= layer 1: K=128, F=512, H=4, C=128 =================
    {
        int K = 128, F = 512;
        dim3 grid(4 * F / 128, cdiv(N, 128));
        k_mma4<<<grid, 256, MMA_SMEM>>>(x, Wq1, bq1, q, Wk1, bk1, k, Wv1, bv1, v, Ws1, bs1, sOut, N, K, F);
        k_alphaC<4, 128><<<cdiv(N * 32, TB), TB>>>(src, q, k, N, 0.08838834764831845f);
        k_aggC<4, 128><<<cdiv(N * 32, TB), TB>>>(src, v, sOut, ln1g, ln1b, hb, N);
    }
    // ================= layer 2: K=512, F=256, H=4, C=64 =================
    {
        int K = 512, F = 256;
        dim3 grid(4 * F / 128, cdiv(N, 128));
        k_mma4<<<grid, 256, MMA_SMEM>>>(hb, Wq2, bq2, q, Wk2, bk2, k, Wv2, bv2, v, Ws2, bs2, sOut, N, K, F);
        k_alphaC<4, 64><<<cdiv(N * 32, TB), TB>>>(src, q, k, N, 0.125f);
        k_aggC<4, 64><<<cdiv(N * 32, TB), TB>>>(src, v, sOut, ln2g, ln2b, hb, N);
    }
    // ================= layer 3: K=256, F=2, H=1, C=2 =================
    {
        k_gemm3f<<<cdiv(N * 32, TB), TB>>>(hb, Wq3, bq3, Wk3, bk3, Wv3, bv3, Ws3, bs3,
                                           q, k, v, sOut, N);
        k_alpha3<<<cdiv(E, TB), TB>>>(src, dst, q, k, E, 0.7071067811865475f);
        k_final3<<<cdiv(N, TB), TB>>>(src, v, sOut, out, N);
    }
}

// round 10
// speedup vs baseline: 7.8603x; 1.0479x over previous
#include <cuda_runtime.h>
#include <cstdint>
#include <stdint.h>
#include <math.h>

#define NN 50000
#define EE 400000

// ---------------- scratch (device globals) ----------------
__device__ float g_y[(size_t)NN * 2048];     // q|k|v|s slices, each NN*512
__device__ float g_h[(size_t)NN * 512];
__device__ float g_alpha[(size_t)EE * 4];
__device__ int   g_rowptr[NN + 1];
__device__ int   g_cursor[NN];
__device__ int   g_perm[EE];
__device__ int   g_chunksum[256];

// ---------------- CSR build (by dst) ----------------
__global__ void k_zero_rowptr(int n) {
    int i = blockIdx.x * blockDim.x + threadIdx.x;
    if (i < n) g_rowptr[i] = 0;
}
__global__ void k_count(const int* __restrict__ dst, int E) {
    int e = blockIdx.x * blockDim.x + threadIdx.x;
    if (e < E) atomicAdd(&g_rowptr[dst[e] + 1], 1);
}
__global__ void k_block_sums(int n) {
    __shared__ int sh[256];
    int i = blockIdx.x * 256 + threadIdx.x;
    sh[threadIdx.x] = (i < n) ? g_rowptr[i] : 0;
    __syncthreads();
    for (int o = 128; o > 0; o >>= 1) {
        if (threadIdx.x < o) sh[threadIdx.x] += sh[threadIdx.x + o];
        __syncthreads();
    }
    if (threadIdx.x == 0) g_chunksum[blockIdx.x] = sh[0];
}
__global__ void k_scan_chunks(int nch) {
    if (threadIdx.x == 0 && blockIdx.x == 0) {
        int running = 0;
        for (int i = 0; i < nch; i++) {
            int t = g_chunksum[i];
            g_chunksum[i] = running;
            running += t;
        }
    }
}
__global__ void k_block_scan(int n) {
    __shared__ int sh[256];
    int i = blockIdx.x * 256 + threadIdx.x;
    int t = threadIdx.x;
    sh[t] = (i < n) ? g_rowptr[i] : 0;
    __syncthreads();
    for (int o = 1; o < 256; o <<= 1) {
        int v = sh[t];
        int u = (t >= o) ? sh[t - o] : 0;
        __syncthreads();
        sh[t] = v + u;
        __syncthreads();
    }
    if (i < n) g_rowptr[i] = sh[t] + g_chunksum[blockIdx.x];
}
__global__ void k_cursor(int n) {
    int i = blockIdx.x * blockDim.x + threadIdx.x;
    if (i < n) g_cursor[i] = g_rowptr[i];
}
__global__ void k_scatter(const int* __restrict__ dst, int E) {
    int e = blockIdx.x * blockDim.x + threadIdx.x;
    if (e < E) {
        int p = atomicAdd(&g_cursor[dst[e]], 1);
        g_perm[p] = e;
    }
}

// ---------------- TF32x3 tensor-core GEMM ----------------
__device__ __forceinline__ uint32_t f2tf(float x) {
    uint32_t r;
    asm("cvt.rna.tf32.f32 %0, %1;" : "=r"(r) : "f"(x));
    return r;
}
__device__ __forceinline__ void mma_tf32(float* c, const uint32_t* a, const uint32_t* b) {
    asm volatile(
        "mma.sync.aligned.m16n8k8.row.col.f32.tf32.tf32.f32 "
        "{%0,%1,%2,%3}, {%4,%5,%6,%7}, {%8,%9}, {%0,%1,%2,%3};"
        : "+f"(c[0]), "+f"(c[1]), "+f"(c[2]), "+f"(c[3])
        : "r"(a[0]), "r"(a[1]), "r"(a[2]), "r"(a[3]), "r"(b[0]), "r"(b[1]));
}

#define AST 36     // A smem stride [m][k]
#define BST 136    // B smem stride [k][n]
#define MMA_SMEM ((2 * 128 * AST + 2 * 32 * BST) * 4)   // 71680 B

__global__ void __launch_bounds__(256) k_mma4(const float* __restrict__ Ag,
                                              const float* __restrict__ W0, const float* __restrict__ b0, float* __restrict__ o0,
                                              const float* __restrict__ W1, const float* __restrict__ b1, float* __restrict__ o1,
                                              const float* __restrict__ W2, const float* __restrict__ b2, float* __restrict__ o2,
                                              const float* __restrict__ W3, const float* __restrict__ b3, float* __restrict__ o3,
                                              int M, int K, int F) {
    extern __shared__ float sm[];
    float* As_hi = sm;
    float* As_lo = As_hi + 128 * AST;
    float* Bs_hi = As_lo + 128 * AST;
    float* Bs_lo = Bs_hi + 32 * BST;

    int tid = threadIdx.x;
    int warp = tid >> 5, lane = tid & 31;
    int wm = warp >> 2;
    int wn = warp & 3;
    int gid = lane >> 2;
    int l4 = lane & 3;

    int nb = F / 128;
    int bsel = blockIdx.x / nb;
    int bn = blockIdx.x % nb;
    int bm = blockIdx.y;
    const float* W = bsel == 0 ? W0 : bsel == 1 ? W1 : bsel == 2 ? W2 : W3;
    const float* bias = bsel == 0 ? b0 : bsel == 1 ? b1 : bsel == 2 ? b2 : b3;
    float* outp = bsel == 0 ? o0 : bsel == 1 ? o1 : bsel == 2 ? o2 : o3;

    float acc[4][4][4];
#pragma unroll
    for (int i = 0; i < 4; i++)
#pragma unroll
        for (int j = 0; j < 4; j++)
#pragma unroll
            for (int r = 0; r < 4; r++) acc[i][j][r] = 0.f;

    for (int k0 = 0; k0 < K; k0 += 32) {
        __syncthreads();
#pragma unroll
        for (int i = 0; i < 4; i++) {
            int r = (tid >> 3) + i * 32;
            int fc = (tid & 7) * 4;
            int gr = bm * 128 + r;
            float4 v = make_float4(0.f, 0.f, 0.f, 0.f);
            if (gr < M) v = *(const float4*)(Ag + (size_t)gr * K + k0 + fc);
            float4 h, l;
            h.x = __uint_as_float(f2tf(v.x)); l.x = __uint_as_float(f2tf(v.x - h.x));
            h.y = __uint_as_float(f2tf(v.y)); l.y = __uint_as_float(f2tf(v.y - h.y));
            h.z = __uint_as_float(f2tf(v.z)); l.z = __uint_as_float(f2tf(v.z - h.z));
            h.w = __uint_as_float(f2tf(v.w)); l.w = __uint_as_float(f2tf(v.w - h.w));
            *(float4*)(As_hi + r * AST + fc) = h;
            *(float4*)(As_lo + r * AST + fc) = l;
        }
        {
            int kk = tid >> 3;
            const float* Wrow = W + (size_t)(k0 + kk) * F + bn * 128;
#pragma unroll
            for (int i = 0; i < 4; i++) {
                int n = (tid & 7) * 4 + i * 32;
                float4 v = *(const float4*)(Wrow + n);
                float4 h, l;
                h.x = __uint_as_float(f2tf(v.x)); l.x = __uint_as_float(f2tf(v.x - h.x));
                h.y = __uint_as_float(f2tf(v.y)); l.y = __uint_as_float(f2tf(v.y - h.y));
                h.z = __uint_as_float(f2tf(v.z)); l.z = __uint_as_float(f2tf(v.z - h.z));
                h.w = __uint_as_float(f2tf(v.w)); l.w = __uint_as_float(f2tf(v.w - h.w));
                *(float4*)(Bs_hi + kk * BST + n) = h;
                *(float4*)(Bs_lo + kk * BST + n) = l;
            }
        }
        __syncthreads();

#pragma unroll
        for (int ks = 0; ks < 32; ks += 8) {
            uint32_t ah[4][4], al[4][4], bh[4][2], bl[4][2];
#pragma unroll
            for (int tm = 0; tm < 4; tm++) {
                int m0 = wm * 64 + tm * 16 + gid;
                const float* ph = As_hi + m0 * AST + ks + l4;
                const float* pl = As_lo + m0 * AST + ks + l4;
                ah[tm][0] = __float_as_uint(ph[0]);
                ah[tm][1] = __float_as_uint(ph[8 * AST]);
                ah[tm][2] = __float_as_uint(ph[4]);
                ah[tm][3] = __float_as_uint(ph[8 * AST + 4]);
                al[tm][0] = __float_as_uint(pl[0]);
                al[tm][1] = __float_as_uint(pl[8 * AST]);
                al[tm][2] = __float_as_uint(pl[4]);
                al[tm][3] = __float_as_uint(pl[8 * AST + 4]);
            }
#pragma unroll
            for (int tn = 0; tn < 4; tn++) {
                int n0 = wn * 32 + tn * 8 + gid;
                const float* ph = Bs_hi + (ks + l4) * BST + n0;
                const float* pl = Bs_lo + (ks + l4) * BST + n0;
                bh[tn][0] = __float_as_uint(ph[0]);
                bh[tn][1] = __float_as_uint(ph[4 * BST]);
                bl[tn][0] = __float_as_uint(pl[0]);
                bl[tn][1] = __float_as_uint(pl[4 * BST]);
            }
#pragma unroll
            for (int tm = 0; tm < 4; tm++)
#pragma unroll
                for (int tn = 0; tn < 4; tn++) {
                    mma_tf32(acc[tm][tn], ah[tm], bh[tn]);
                    mma_tf32(acc[tm][tn], ah[tm], bl[tn]);
                    mma_tf32(acc[tm][tn], al[tm], bh[tn]);
                }
        }
    }

#pragma unroll
    for (int tm = 0; tm < 4; tm++) {
        int r0 = bm * 128 + wm * 64 + tm * 16 + gid;
        int r1 = r0 + 8;
#pragma unroll
        for (int tn = 0; tn < 4; tn++) {
            int c = bn * 128 + wn * 32 + tn * 8 + l4 * 2;
            if (r0 < M) {
                outp[(size_t)r0 * F + c] = acc[tm][tn][0] + bias[c];
                outp[(size_t)r0 * F + c + 1] = acc[tm][tn][1] + bias[c + 1];
            }
            if (r1 < M) {
                outp[(size_t)r1 * F + c] = acc[tm][tn][2] + bias[c];
                outp[(size_t)r1 * F + c + 1] = acc[tm][tn][3] + bias[c + 1];
            }
        }
    }
}

// ---------------- CSR dst-side score: warp per node, q cached in registers ----------------
template <int H, int C>
__global__ void k_alphaC(const int* __restrict__ src,
                         const float* __restrict__ q, const float* __restrict__ k,
                         int n, float scale) {
    constexpr int F = H * C;
    constexpr int T = F / 128;
    int node = (blockIdx.x * blockDim.x + threadIdx.x) >> 5;
    int lane = threadIdx.x & 31;
    if (node >= n) return;
    int s0 = g_rowptr[node], s1 = g_rowptr[node + 1];
    if (s0 == s1) return;

    float4 qr[T];
    const float4* qp = (const float4*)(q + (size_t)node * F);
#pragma unroll
    for (int t = 0; t < T; t++) qr[t] = qp[lane + 32 * t];

    for (int j = s0; j < s1; j++) {
        int e = g_perm[j];
        const float4* kp = (const float4*)(k + (size_t)src[e] * F);
        float acc[H];
#pragma unroll
        for (int h = 0; h < H; h++) acc[h] = 0.f;
#pragma unroll
        for (int t = 0; t < T; t++) {
            float4 a = qr[t], b = kp[lane + 32 * t];
            float d = a.x * b.x + a.y * b.y + a.z * b.z + a.w * b.w;
            if constexpr (C == 128) {
                acc[t] += d;
            } else {
                if (lane < 16) acc[2 * t] += d;
                else acc[2 * t + 1] += d;
            }
        }
#pragma unroll
        for (int h = 0; h < H; h++) {
            float v = acc[h];
#pragma unroll
            for (int o = 16; o; o >>= 1) v += __shfl_xor_sync(0xffffffffu, v, o);
            if (lane == 0) g_alpha[(size_t)e * H + h] = v * scale;
        }
    }
}

// ---------------- CSR warp-per-node agg (float4): softmax + aggregate + skip + LN + ELU ----
template <int H, int C>
__global__ void k_aggC(const int* __restrict__ src,
                       const float* __restrict__ v, const float* __restrict__ sskip,
                       const float* __restrict__ lng, const float* __restrict__ lnb,
                       float* __restrict__ outp, int n) {
    constexpr int F = H * C, V = F / 128;  // float4 per lane
    int node = (blockIdx.x * blockDim.x + threadIdx.x) >> 5;
    int lane = threadIdx.x & 31;
    if (node >= n) return;
    int s0 = g_rowptr[node], s1 = g_rowptr[node + 1], deg = s1 - s0;

    float m[H], dn[H];
#pragma unroll
    for (int h = 0; h < H; h++) {
        float mv = -INFINITY;
        for (int j = lane; j < deg; j += 32)
            mv = fmaxf(mv, g_alpha[(size_t)g_perm[s0 + j] * H + h]);
#pragma unroll
        for (int o = 16; o; o >>= 1) mv = fmaxf(mv, __shfl_xor_sync(0xffffffffu, mv, o));
        m[h] = mv;
        float sv = 0.f;
        for (int j = lane; j < deg; j += 32)
            sv += __expf(g_alpha[(size_t)g_perm[s0 + j] * H + h] - mv);
#pragma unroll
        for (int o = 16; o; o >>= 1) sv += __shfl_xor_sync(0xffffffffu, sv, o);
        dn[h] = 1.f / (sv + 1e-16f);
    }

    float4 acc[V];
#pragma unroll
    for (int t = 0; t < V; t++) acc[t] = make_float4(0.f, 0.f, 0.f, 0.f);

    for (int j = 0; j < deg; j++) {
        int e = g_perm[s0 + j];
        int sv = src[e];
        float w[H];
#pragma unroll
        for (int h = 0; h < H; h++)
            w[h] = __expf(g_alpha[(size_t)e * H + h] - m[h]) * dn[h];
        const float4* vr = (const float4*)(v + (size_t)sv * F);
#pragma unroll
        for (int t = 0; t < V; t++) {
            // head of float4 (lane + 32t): C=128 -> t ; C=64 -> 2t + (lane>=16)
            float ww;
            if constexpr (C == 128) ww = w[t];
            else ww = (lane < 16) ? w[2 * t] : w[2 * t + 1];
            float4 b = vr[lane + 32 * t];
            acc[t].x = fmaf(ww, b.x, acc[t].x);
            acc[t].y = fmaf(ww, b.y, acc[t].y);
            acc[t].z = fmaf(ww, b.z, acc[t].z);
            acc[t].w = fmaf(ww, b.w, acc[t].w);
        }
    }
    // skip
    const float4* sr = (const float4*)(sskip + (size_t)node * F);
#pragma unroll
    for (int t = 0; t < V; t++) {
        float4 b = sr[lane + 32 * t];
        acc[t].x += b.x; acc[t].y += b.y; acc[t].z += b.z; acc[t].w += b.w;
    }

    // LayerNorm + ELU
    float s = 0.f;
#pragma unroll
    for (int t = 0; t < V; t++) s += acc[t].x + acc[t].y + acc[t].z + acc[t].w;
#pragma unroll
    for (int o = 16; o; o >>= 1) s += __shfl_xor_sync(0xffffffffu, s, o);
    float mean = s / (float)F;
    float vs = 0.f;
#pragma unroll
    for (int t = 0; t < V; t++) {
        float dx = acc[t].x - mean, dy = acc[t].y - mean,
              dz = acc[t].z - mean, dw = acc[t].w - mean;
        vs = fmaf(dx, dx, vs); vs = fmaf(dy, dy, vs);
        vs = fmaf(dz, dz, vs); vs = fmaf(dw, dw, vs);
    }
#pragma unroll
    for (int o = 16; o; o >>= 1) vs += __shfl_xor_sync(0xffffffffu, vs, o);
    float r = rsqrtf(vs / (float)F + 1e-5f);
    const float4* gp = (const float4*)lng;
    const float4* bp = (const float4*)lnb;
    float4* op = (float4*)(outp + (size_t)node * F);
#pragma unroll
    for (int t = 0; t < V; t++) {
        int f4 = lane + 32 * t;
        float4 g = gp[f4], bb = bp[f4], o4;
        float tx = (acc[t].x - mean) * r * g.x + bb.x;
        float ty = (acc[t].y - mean) * r * g.y + bb.y;
        float tz = (acc[t].z - mean) * r * g.z + bb.z;
        float tw = (acc[t].w - mean) * r * g.w + bb.w;
        o4.x = tx > 0.f ? tx : expm1f(tx);
        o4.y = ty > 0.f ? ty : expm1f(ty);
        o4.z = tz > 0.f ? tz : expm1f(tz);
        o4.w = tw > 0.f ? tw : expm1f(tw);
        op[f4] = o4;
    }
}

// ---------------- layer 3: fused projection, warp per node ----------------
__global__ void k_gemm3f(const float* __restrict__ X,
                         const float* __restrict__ Wq, const float* __restrict__ bq,
                         const float* __restrict__ Wk, const float* __restrict__ bk,
                         const float* __restrict__ Wv, const float* __restrict__ bv,
                         const float* __restrict__ Ws, const float* __restrict__ bs,
                         float* __restrict__ q, float* __restrict__ k,
                         float* __restrict__ v, float* __restrict__ sOut, int n) {
    int node = (blockIdx.x * blockDim.x + threadIdx.x) >> 5;
    int lane = threadIdx.x & 31;
    if (node >= n) return;
    const float* x = X + (size_t)node * 256;
    float a[8];
#pragma unroll
    for (int i = 0; i < 8; i++) a[i] = 0.f;
#pragma unroll
    for (int t = 0; t < 8; t++) {
        int i = lane + 32 * t;
        float xv = x[i];
        a[0] = fmaf(xv, Wq[i * 2], a[0]);
        a[1] = fmaf(xv, Wq[i * 2 + 1], a[1]);
        a[2] = fmaf(xv, Wk[i * 2], a[2]);
        a[3] = fmaf(xv, Wk[i * 2 + 1], a[3]);
        a[4] = fmaf(xv, Wv[i * 2], a[4]);
        a[5] = fmaf(xv, Wv[i * 2 + 1], a[5]);
        a[6] = fmaf(xv, Ws[i * 2], a[6]);
        a[7] = fmaf(xv, Ws[i * 2 + 1], a[7]);
    }
#pragma unroll
    for (int i = 0; i < 8; i++) {
#pragma unroll
        for (int o = 16; o; o >>= 1) a[i] += __shfl_xor_sync(0xffffffffu, a[i], o);
    }
    if (lane == 0) {
        q[(size_t)node * 2 + 0] = a[0] + bq[0];
        q[(size_t)node * 2 + 1] = a[1] + bq[1];
        k[(size_t)node * 2 + 0] = a[2] + bk[0];
        k[(size_t)node * 2 + 1] = a[3] + bk[1];
        v[(size_t)node * 2 + 0] = a[4] + bv[0];
        v[(size_t)node * 2 + 1] = a[5] + bv[1];
        sOut[(size_t)node * 2 + 0] = a[6] + bs[0];
        sOut[(size_t)node * 2 + 1] = a[7] + bs[1];
    }
}

// ---------------- layer-3 score: thread-per-edge ----------------
__global__ void k_alpha3(const int* __restrict__ src, const int* __restrict__ dst,
                         const float* __restrict__ q, const float* __restrict__ k,
                         int E, float scale) {
    int e = blockIdx.x * blockDim.x + threadIdx.x;
    if (e >= E) return;
    const float* qp = q + (size_t)dst[e] * 2;
    const float* kp = k + (size_t)src[e] * 2;
    g_alpha[e] = (qp[0] * kp[0] + qp[1] * kp[1]) * scale;
}

// ---------------- layer 3 CSR finalize ----------------
__global__ void k_final3(const int* __restrict__ src,
                         const float* __restrict__ v2, const float* __restrict__ s3,
                         float* __restrict__ out, int n) {
    int i = blockIdx.x * blockDim.x + threadIdx.x;
    if (i >= n) return;
    int s0 = g_rowptr[i], s1 = g_rowptr[i + 1];
    float m = -INFINITY;
    for (int j = s0; j < s1; j++) m = fmaxf(m, g_alpha[g_perm[j]]);
    float a0 = 0.f, a1 = 0.f;
    if (s1 > s0) {
        float dnm = 0.f;
        for (int j = s0; j < s1; j++) dnm += __expf(g_alpha[g_perm[j]] - m);
        float inv = 1.f / (dnm + 1e-16f);
        for (int j = s0; j < s1; j++) {
            int e = g_perm[j];
            float w = __expf(g_alpha[e] - m) * inv;
            const float* vr = v2 + (size_t)src[e] * 2;
            a0 = fmaf(w, vr[0], a0);
            a1 = fmaf(w, vr[1], a1);
        }
    }
    float h0 = a0 + s3[(size_t)i * 2 + 0];
    float h1 = a1 + s3[(size_t)i * 2 + 1];
    float mx = fmaxf(h0, h1);
    float lse = mx + logf(expf(h0 - mx) + expf(h1 - mx));
    out[2 * i + 0] = h0 - lse;
    out[2 * i + 1] = h1 - lse;
}

// ---------------- launch ----------------
static inline int cdiv(int a, int b) { return (a + b - 1) / b; }

extern "C" void kernel_launch(void* const* d_in, const int* in_sizes, int n_in,
                              void* d_out, int out_size) {
    const float* x = (const float*)d_in[0];
    const int* ei = (const int*)d_in[1];
    const int N = in_sizes[0] / 128;
    const int E = in_sizes[1] / 2;
    const int* src = ei;
    const int* dst = ei + E;

    const float *Wq1 = (const float*)d_in[2],  *bq1 = (const float*)d_in[3];
    const float *Wk1 = (const float*)d_in[4],  *bk1 = (const float*)d_in[5];
    const float *Wv1 = (const float*)d_in[6],  *bv1 = (const float*)d_in[7];
    const float *Ws1 = (const float*)d_in[8],  *bs1 = (const float*)d_in[9];
    const float *Wq2 = (const float*)d_in[10], *bq2 = (const float*)d_in[11];
    const float *Wk2 = (const float*)d_in[12], *bk2 = (const float*)d_in[13];
    const float *Wv2 = (const float*)d_in[14], *bv2 = (const float*)d_in[15];
    const float *Ws2 = (const float*)d_in[16], *bs2 = (const float*)d_in[17];
    const float *Wq3 = (const float*)d_in[18], *bq3 = (const float*)d_in[19];
    const float *Wk3 = (const float*)d_in[20], *bk3 = (const float*)d_in[21];
    const float *Wv3 = (const float*)d_in[22], *bv3 = (const float*)d_in[23];
    const float *Ws3 = (const float*)d_in[24], *bs3 = (const float*)d_in[25];
    const float *ln1g = (const float*)d_in[26], *ln1b = (const float*)d_in[27];
    const float *ln2g = (const float*)d_in[28], *ln2b = (const float*)d_in[29];
    float* out = (float*)d_out;

    static float* yb = nullptr;
    if (!yb) { void* p; cudaGetSymbolAddress(&p, g_y); yb = (float*)p; }
    float* q = yb;
    float* k = yb + (size_t)NN * 512;
    float* v = yb + (size_t)NN * 1024;
    float* sOut = yb + (size_t)NN * 1536;
    static float* hb = nullptr;
    if (!hb) { void* p; cudaGetSymbolAddress(&p, g_h); hb = (float*)p; }

    static bool cfg = false;
    static cudaStream_t s2;
    static cudaEvent_t evFork, evJoin;
    if (!cfg) {
        cudaFuncSetAttribute(k_mma4, cudaFuncAttributeMaxDynamicSharedMemorySize, MMA_SMEM);
        cudaStreamCreateWithFlags(&s2, cudaStreamNonBlocking);
        cudaEventCreateWithFlags(&evFork, cudaEventDisableTiming);
        cudaEventCreateWithFlags(&evJoin, cudaEventDisableTiming);
        cfg = true;
    }

    const int TB = 256;

    // ---- fork: CSR build on s2, overlapped with layer-1 GEMM on default stream ----
    cudaEventRecord(evFork, 0);
    cudaStreamWaitEvent(s2, evFork, 0);

    int n1 = N + 1;
    int nch = cdiv(n1, 256);
    k_zero_rowptr<<<cdiv(n1, TB), TB, 0, s2>>>(n1);
    k_count<<<cdiv(E, TB), TB, 0, s2>>>(dst, E);
    k_block_sums<<<nch, 256, 0, s2>>>(n1);
    k_scan_chunks<<<1, 32, 0, s2>>>(nch);
    k_block_scan<<<nch, 256, 0, s2>>>(n1);
    k_cursor<<<cdiv(N, TB), TB, 0, s2>>>(N);
    k_scatter<<<cdiv(E, TB), TB, 0, s2>>>(dst, E);
    cudaEventRecord(evJoin, s2);

    // ================= layer 1: K=128, F=512, H=4, C=128 =================
    {
        int K = 128, F = 512;
        dim3 grid(4 * F / 128, cdiv(N, 128));
        k_mma4<<<grid, 256, MMA_SMEM>>>(x, Wq1, bq1, q, Wk1, bk1, k, Wv1, bv1, v, Ws1, bs1, sOut, N, K, F);
        cudaStreamWaitEvent(0, evJoin, 0);   // join CSR before edge phase
        k_alphaC<4, 128><<<cdiv(N * 32, TB), TB>>>(src, q, k, N, 0.08838834764831845f);
        k_aggC<4, 128><<<cdiv(N * 32, TB), TB>>>(src, v, sOut, ln1g, ln1b, hb, N);
    }
    // ================= layer 2: K=512, F=256, H=4, C=64 =================
    {
        int K = 512, F = 256;
        dim3 grid(4 * F / 128, cdiv(N, 128));
        k_mma4<<<grid, 256, MMA_SMEM>>>(hb, Wq2, bq2, q, Wk2, bk2, k, Wv2, bv2, v, Ws2, bs2, sOut, N, K, F);
        k_alphaC<4, 64><<<cdiv(N * 32, TB), TB>>>(src, q, k, N, 0.125f);
        k_aggC<4, 64><<<cdiv(N * 32, TB), TB>>>(src, v, sOut, ln2g, ln2b, hb, N);
    }
    // ================= layer 3: K=256, F=2, H=1, C=2 =================
    {
        k_gemm3f<<<cdiv(N * 32, TB), TB>>>(hb, Wq3, bq3, Wk3, bk3, Wv3, bv3, Ws3, bs3,
                                           q, k, v, sOut, N);
        k_alpha3<<<cdiv(E, TB), TB>>>(src, dst, q, k, E, 0.7071067811865475f);
        k_final3<<<cdiv(N, TB), TB>>>(src, v, sOut, out, N);
    }
}